// round 13
// baseline (speedup 1.0000x reference)
#include <cuda_runtime.h>
#include <cuda_bf16.h>
#include <cstdint>

#define NMAX 50000
#define EMAX 800000
#define F_IN 100
#define HID  128
#define H2D  64

// ---- scratch ----
__device__ int   g_deg[NMAX];
__device__ int   g_off[NMAX + 1];
__device__ int   g_cur[NMAX];
__device__ int   g_csr[EMAX];
__device__ int   g_bsum[256];
__device__ int   g_boff[256];
// invdeg | agg[N*128] | t1[N*128] | t2[N*64] | bn(768)
__device__ float g_scratch[NMAX * 321 + 768];

// split weights bf16 hi/lo, transposed [NC][Kpad]
#define WOFF_L1  0
#define WOFF_R1  14336
#define WOFF_L2  28672
#define WOFF_R2  45056
#define WOFF_M1  61440
#define WOFF_M2  77824
#define WTOTAL   86016
__device__ __nv_bfloat16 g_wh[WTOTAL];
__device__ __nv_bfloat16 g_wl[WTOTAL];

// ---------------------------------------------------------------------------
__global__ void zero_kernel(int* __restrict__ p, int n) {
    int i = blockIdx.x * blockDim.x + threadIdx.x;
    for (; i < n; i += gridDim.x * blockDim.x) p[i] = 0;
}

__global__ void deg_kernel(const int* __restrict__ dst, int* __restrict__ deg, int E) {
    int e = blockIdx.x * blockDim.x + threadIdx.x;
    if (e < E) atomicAdd(&deg[dst[e]], 1);
}

// ---- three-phase parallel exclusive scan ----
__global__ void block_sums(const int* __restrict__ deg, int* __restrict__ bsum, int N) {
    int i = blockIdx.x * 256 + threadIdx.x;
    int lane = threadIdx.x & 31, w = threadIdx.x >> 5;
    int v = (i < N) ? deg[i] : 0;
#pragma unroll
    for (int o = 16; o; o >>= 1) v += __shfl_down_sync(~0u, v, o);
    __shared__ int ws[8];
    if (lane == 0) ws[w] = v;
    __syncthreads();
    if (threadIdx.x == 0) {
        int s = 0;
#pragma unroll
        for (int j = 0; j < 8; j++) s += ws[j];
        bsum[blockIdx.x] = s;
    }
}

// 1 block, 256 threads; exclusive-scans nb (<=256) partials; zeroes BN sums
__global__ void scan_partials(const int* __restrict__ bsum, int* __restrict__ boff,
                              int nb, float* __restrict__ bnzero) {
    int t = threadIdx.x, lane = t & 31, w = t >> 5;
    for (int i = t; i < 384; i += 256) bnzero[i] = 0.f;
    int d = (t < nb) ? bsum[t] : 0;
    int v = d;
#pragma unroll
    for (int o = 1; o < 32; o <<= 1) {
        int u = __shfl_up_sync(~0u, v, o);
        if (lane >= o) v += u;
    }
    __shared__ int ws[8];
    if (lane == 31) ws[w] = v;
    __syncthreads();
    int add = 0;
#pragma unroll
    for (int j = 0; j < 8; j++) if (j < w) add += ws[j];
    boff[t] = v - d + add;
}

__global__ void offsets_kernel(const int* __restrict__ deg, const int* __restrict__ boff,
                               int* __restrict__ off, int* __restrict__ cur,
                               float* __restrict__ invdeg, int N, int E) {
    int i = blockIdx.x * 256 + threadIdx.x;
    int t = threadIdx.x, lane = t & 31, w = t >> 5;
    int d = (i < N) ? deg[i] : 0;
    int v = d;
#pragma unroll
    for (int o = 1; o < 32; o <<= 1) {
        int u = __shfl_up_sync(~0u, v, o);
        if (lane >= o) v += u;
    }
    __shared__ int ws[8];
    if (lane == 31) ws[w] = v;
    __syncthreads();
    int add = 0;
#pragma unroll
    for (int j = 0; j < 8; j++) if (j < w) add += ws[j];
    int excl = v - d + add + boff[blockIdx.x];
    if (i < N) {
        off[i] = excl;
        cur[i] = excl;
        invdeg[i] = 1.0f / fmaxf((float)d, 1.0f);
    }
    if (i == 0) off[N] = E;
}

__global__ void fill_kernel(const int* __restrict__ src, const int* __restrict__ dst,
                            int* __restrict__ cur, int* __restrict__ csr, int E) {
    int e = blockIdx.x * blockDim.x + threadIdx.x;
    if (e < E) {
        int pos = atomicAdd(&cur[dst[e]], 1);
        csr[pos] = src[e];
    }
}

// split + transpose all 6 weight matrices into bf16 hi/lo, [NC][Kpad]
__global__ void prep_weights(const float* __restrict__ Wl1, const float* __restrict__ Wr1,
                             const float* __restrict__ Wl2, const float* __restrict__ Wr2,
                             const float* __restrict__ W1,  const float* __restrict__ W2,
                             __nv_bfloat16* __restrict__ wh, __nv_bfloat16* __restrict__ wl) {
    int i = blockIdx.x * blockDim.x + threadIdx.x;
    if (i >= WTOTAL) return;
    const float* W; int K, KP, NC, local;
    if (i < WOFF_L2) {
        if (i < WOFF_R1) { W = Wl1; local = i; }
        else             { W = Wr1; local = i - WOFF_R1; }
        K = 100; KP = 112; NC = 128;
    } else if (i < WOFF_M2) {
        if (i < WOFF_R2)      { W = Wl2; local = i - WOFF_L2; }
        else if (i < WOFF_M1) { W = Wr2; local = i - WOFF_R2; }
        else                  { W = W1;  local = i - WOFF_M1; }
        K = 128; KP = 128; NC = 128;
    } else {
        W = W2; local = i - WOFF_M2; K = 128; KP = 128; NC = 64;
    }
    int n = local / KP, k = local - n * KP;
    float v = (k < K) ? W[k * NC + n] : 0.f;
    __nv_bfloat16 h = __float2bfloat16_rn(v);
    wh[i] = h;
    wl[i] = __float2bfloat16_rn(v - __bfloat162float(h));
}

// ---------------------------------------------------------------------------
// gather aggregation: warp per dst node, lane owns one float4 feature group.
// ---------------------------------------------------------------------------
template <int F4>
__global__ void gather_agg(const float4* __restrict__ x4, const int* __restrict__ csr,
                           const int* __restrict__ off, const float* __restrict__ invdeg,
                           float4* __restrict__ agg, int N) {
    int w = (blockIdx.x * blockDim.x + threadIdx.x) >> 5;
    int lane = threadIdx.x & 31;
    if (w >= N || lane >= F4) return;
    int o = off[w];
    int d = off[w + 1] - o;
    float4 acc = make_float4(0.f, 0.f, 0.f, 0.f);
    int j = 0;
    for (; j + 2 <= d; j += 2) {
        int s0 = __ldg(&csr[o + j]);
        int s1 = __ldg(&csr[o + j + 1]);
        float4 v0 = __ldg(&x4[(size_t)s0 * F4 + lane]);
        float4 v1 = __ldg(&x4[(size_t)s1 * F4 + lane]);
        acc.x += v0.x; acc.y += v0.y; acc.z += v0.z; acc.w += v0.w;
        acc.x += v1.x; acc.y += v1.y; acc.z += v1.z; acc.w += v1.w;
    }
    if (j < d) {
        int s0 = __ldg(&csr[o + j]);
        float4 v0 = __ldg(&x4[(size_t)s0 * F4 + lane]);
        acc.x += v0.x; acc.y += v0.y; acc.z += v0.z; acc.w += v0.w;
    }
    float iv = invdeg[w];
    agg[(size_t)w * F4 + lane] = make_float4(acc.x * iv, acc.y * iv, acc.z * iv, acc.w * iv);
}

// ---------------------------------------------------------------------------
// Tensor-core GEMM, two-term bf16 split (3 MMAs), ldmatrix frags,
// double-buffered smem, cp.async for B tiles. BM=64 tiles for occupancy 3.
// ---------------------------------------------------------------------------
__device__ __forceinline__ uint32_t smem_u32(const void* p) {
    return (uint32_t)__cvta_generic_to_shared(p);
}

#define LDSM4(R, a)                                                             \
    asm volatile("ldmatrix.sync.aligned.m8n8.x4.shared.b16 {%0,%1,%2,%3}, [%4];"\
                 : "=r"((R)[0]), "=r"((R)[1]), "=r"((R)[2]), "=r"((R)[3])       \
                 : "r"(a))

#define MMA16816(C, A, b0, b1)                                                  \
    asm volatile("mma.sync.aligned.m16n8k16.row.col.f32.bf16.bf16.f32 "         \
                 "{%0,%1,%2,%3}, {%4,%5,%6,%7}, {%8,%9}, {%0,%1,%2,%3};"        \
                 : "+f"((C)[0]), "+f"((C)[1]), "+f"((C)[2]), "+f"((C)[3])       \
                 : "r"((A)[0]), "r"((A)[1]), "r"((A)[2]), "r"((A)[3]),          \
                   "r"(b0), "r"(b1))

#define CP_ASYNC16(smem_addr, gptr)                                             \
    asm volatile("cp.async.ca.shared.global [%0], [%1], 16;"                    \
                 :: "r"(smem_addr), "l"(gptr) : "memory")

template <int K1, int KP1, int K2, int KP2, int NC, bool RELU, bool BNRELU, bool STATS>
__global__ __launch_bounds__(256, 3) void mma_gemm(
    const float* __restrict__ A1, const float* __restrict__ A2,
    const __nv_bfloat16* __restrict__ B1h, const __nv_bfloat16* __restrict__ B1l,
    const __nv_bfloat16* __restrict__ B2h, const __nv_bfloat16* __restrict__ B2l,
    const float* __restrict__ bias,
    const float* __restrict__ bnsc, const float* __restrict__ bnsh,
    float* __restrict__ gsum, float* __restrict__ gsumsq,
    float* __restrict__ out, int N) {

    // BM = 64. 8 warps: 4 along M (16 rows each), 2 along N.
    constexpr int NCW = NC / 2;            // 64 or 32 cols per warp
    constexpr int NT = NCW / 8;            // 8 or 4
    constexpr int NH = NCW / 32;           // 2 or 1 (16-col ldsm pairs per half)
    constexpr int C1 = KP1 / 16, C2 = KP2 / 16, NCH = C1 + C2;
    constexpr int BCP = NC * 2;            // 16B chunks per B array per stage

    __shared__ __align__(16) __nv_bfloat16 Ah[2][64][24], Al[2][64][24];
    __shared__ __align__(16) __nv_bfloat16 Bh[2][NC][24],  Bl[2][NC][24];

    const int tid = threadIdx.x, lane = tid & 31, wid = tid >> 5;
    const int wm = wid >> 1, wn = wid & 1;
    const int row0 = blockIdx.x * 64;

    float acc[NT][4];
#pragma unroll
    for (int nt = 0; nt < NT; nt++)
#pragma unroll
        for (int q = 0; q < 4; q++) acc[nt][q] = 0.f;

    float2 av[2];                 // A staging (fp32 -> bf16 split conversion)
    const int kk2 = (tid & 7) * 2;
    const int mr  = tid >> 3;     // 0..31

    auto issue_B = [&](int ch, int st) {
        const __nv_bfloat16 *gh, *gl; int KPE, k0;
        if (ch < C1) { gh = B1h; gl = B1l; KPE = KP1; k0 = ch * 16; }
        else         { gh = B2h; gl = B2l; KPE = KP2; k0 = (ch - C1) * 16; }
#pragma unroll
        for (int j = 0; j < (BCP + 255) / 256; j++) {
            int w = tid + j * 256;
            if (BCP < 256 && w >= BCP) break;
            int n = w >> 1, half = w & 1;
            const __nv_bfloat16* srch = gh + n * KPE + k0 + half * 8;
            const __nv_bfloat16* srcl = gl + n * KPE + k0 + half * 8;
            CP_ASYNC16(smem_u32(&Bh[st][n][half * 8]), srch);
            CP_ASYNC16(smem_u32(&Bl[st][n][half * 8]), srcl);
        }
        asm volatile("cp.async.commit_group;" ::: "memory");
    };

    auto load_A = [&](int ch) {
        const float* A; int K, k0; bool bn;
        if (ch < C1) { A = A1; K = K1; k0 = ch * 16; bn = BNRELU; }
        else         { A = A2; K = K2; k0 = (ch - C1) * 16; bn = false; }
        const int kt = k0 + kk2;
        float s0 = 1.f, h0 = 0.f, s1 = 1.f, h1 = 0.f;
        if (BNRELU && bn) {
            if (kt < K)     { s0 = bnsc[kt];     h0 = bnsh[kt]; }
            if (kt + 1 < K) { s1 = bnsc[kt + 1]; h1 = bnsh[kt + 1]; }
        }
#pragma unroll
        for (int i = 0; i < 2; i++) {
            int row = row0 + mr + i * 32;
            float v0 = 0.f, v1 = 0.f;
            if (row < N) {
                const float* ar = A + (size_t)row * K;
                if (kt + 1 < K) { float2 tv = *(const float2*)(ar + kt); v0 = tv.x; v1 = tv.y; }
                else if (kt < K) { v0 = ar[kt]; }
            }
            if (BNRELU && bn) {
                v0 = fmaxf(fmaf(v0, s0, h0), 0.f);
                v1 = fmaxf(fmaf(v1, s1, h1), 0.f);
            }
            av[i] = make_float2(v0, v1);
        }
    };

    auto store_A = [&](int st) {
#pragma unroll
        for (int i = 0; i < 2; i++) {
            int m = mr + i * 32;
            float2 v = av[i];
            __nv_bfloat162 h2 = __float22bfloat162_rn(v);
            float2 hf = __bfloat1622float2(h2);
            __nv_bfloat162 l2 = __float22bfloat162_rn(make_float2(v.x - hf.x, v.y - hf.y));
            *(uint32_t*)&Ah[st][m][kk2] = *(uint32_t*)&h2;
            *(uint32_t*)&Al[st][m][kk2] = *(uint32_t*)&l2;
        }
    };

    const int arow = (lane & 15), acol = ((lane >> 4) << 3);
    const int brow = (lane & 7) + ((lane & 16) >> 1), bcol = (lane & 8);

    // prologue: fill stage 0
    issue_B(0, 0);
    load_A(0);
    store_A(0);
    asm volatile("cp.async.wait_group 0;" ::: "memory");
    __syncthreads();

    for (int ch = 0; ch < NCH; ch++) {
        const int st = ch & 1;
        if (ch + 1 < NCH) {
            issue_B(ch + 1, st ^ 1);  // async, lands during MMAs
            load_A(ch + 1);           // global loads in flight during MMAs
        }

        uint32_t fah[4], fal[4];
        {
            int m0 = wm * 16;
            LDSM4(fah, smem_u32(&Ah[st][m0 + arow][acol]));
            LDSM4(fal, smem_u32(&Al[st][m0 + arow][acol]));
        }
#pragma unroll
        for (int nh = 0; nh < NH; nh++) {
#pragma unroll
            for (int p = 0; p < 2; p++) {
                uint32_t fbh[4], fbl[4];
                int n0 = wn * NCW + (nh * 2 + p) * 16;
                LDSM4(fbh, smem_u32(&Bh[st][n0 + brow][bcol]));
                LDSM4(fbl, smem_u32(&Bl[st][n0 + brow][bcol]));
#pragma unroll
                for (int hh = 0; hh < 2; hh++) {
                    int nt = nh * 4 + p * 2 + hh;
                    MMA16816(acc[nt], fah, fbh[2 * hh], fbh[2 * hh + 1]);
                    MMA16816(acc[nt], fah, fbl[2 * hh], fbl[2 * hh + 1]);
                    MMA16816(acc[nt], fal, fbh[2 * hh], fbh[2 * hh + 1]);
                }
            }
        }
        if (ch + 1 < NCH) {
            store_A(st ^ 1);
            asm volatile("cp.async.wait_group 0;" ::: "memory");
        }
        __syncthreads();
    }

    // ---- epilogue ----
    const int g = lane >> 2, tg = lane & 3;
    float* s_st = reinterpret_cast<float*>(&Ah[0][0][0]);  // reuse smem
    if (STATS) {
        for (int i = tid; i < 2 * NC; i += 256) s_st[i] = 0.f;
        __syncthreads();
    }

    float ls[NT][2], lq[NT][2];
    if (STATS) {
#pragma unroll
        for (int nt = 0; nt < NT; nt++) { ls[nt][0] = ls[nt][1] = lq[nt][0] = lq[nt][1] = 0.f; }
    }

    {
        int rowA = row0 + wm * 16 + g;
        int rowB = rowA + 8;
#pragma unroll
        for (int nt = 0; nt < NT; nt++) {
            int col = wn * NCW + nt * 8 + tg * 2;
            float b0 = bias[col], b1 = bias[col + 1];
            float v0 = acc[nt][0] + b0, v1 = acc[nt][1] + b1;
            float v2 = acc[nt][2] + b0, v3 = acc[nt][3] + b1;
            if (RELU) {
                v0 = fmaxf(v0, 0.f); v1 = fmaxf(v1, 0.f);
                v2 = fmaxf(v2, 0.f); v3 = fmaxf(v3, 0.f);
            }
            if (rowA < N) {
                *(float2*)&out[(size_t)rowA * NC + col] = make_float2(v0, v1);
                if (STATS) {
                    ls[nt][0] += v0; lq[nt][0] += v0 * v0;
                    ls[nt][1] += v1; lq[nt][1] += v1 * v1;
                }
            }
            if (rowB < N) {
                *(float2*)&out[(size_t)rowB * NC + col] = make_float2(v2, v3);
                if (STATS) {
                    ls[nt][0] += v2; lq[nt][0] += v2 * v2;
                    ls[nt][1] += v3; lq[nt][1] += v3 * v3;
                }
            }
        }
    }

    if (STATS) {
#pragma unroll
        for (int nt = 0; nt < NT; nt++) {
            int col = wn * NCW + nt * 8 + tg * 2;
            atomicAdd(&s_st[col], ls[nt][0]);
            atomicAdd(&s_st[NC + col], lq[nt][0]);
            atomicAdd(&s_st[col + 1], ls[nt][1]);
            atomicAdd(&s_st[NC + col + 1], lq[nt][1]);
        }
        __syncthreads();
        for (int i = tid; i < NC; i += 256) {
            atomicAdd(&gsum[i], s_st[i]);
            atomicAdd(&gsumsq[i], s_st[NC + i]);
        }
    }
}

// ---------------------------------------------------------------------------
__global__ void bn_finalize_kernel(const float* __restrict__ gsum, const float* __restrict__ gsumsq,
                                   const float* __restrict__ gamma, const float* __restrict__ beta,
                                   float* __restrict__ sc, float* __restrict__ sh,
                                   int NC, float invN) {
    int c = threadIdx.x;
    if (c < NC) {
        float m = gsum[c] * invN;
        float var = gsumsq[c] * invN - m * m;
        float inv = rsqrtf(var + 1e-5f);
        float s = inv * gamma[c];
        sc[c] = s;
        sh[c] = beta[c] - m * s;
    }
}

__global__ void final_kernel(const float* __restrict__ t2,
                             const float* __restrict__ sc, const float* __restrict__ sh,
                             const float* __restrict__ W3, const float* __restrict__ b3,
                             float* __restrict__ out, int N) {
    __shared__ float wv[64], scv[64], shv[64];
    if (threadIdx.x < 64) {
        wv[threadIdx.x] = W3[threadIdx.x];
        scv[threadIdx.x] = sc[threadIdx.x];
        shv[threadIdx.x] = sh[threadIdx.x];
    }
    __syncthreads();
    int r = blockIdx.x * blockDim.x + threadIdx.x;
    if (r >= N) return;
    const float4* row = (const float4*)(t2 + (size_t)r * 64);
    float s = 0.f;
#pragma unroll
    for (int q = 0; q < 16; q++) {
        float4 v = row[q];
        int c = q * 4;
        s += fmaxf(fmaf(v.x, scv[c + 0], shv[c + 0]), 0.f) * wv[c + 0];
        s += fmaxf(fmaf(v.y, scv[c + 1], shv[c + 1]), 0.f) * wv[c + 1];
        s += fmaxf(fmaf(v.z, scv[c + 2], shv[c + 2]), 0.f) * wv[c + 2];
        s += fmaxf(fmaf(v.w, scv[c + 3], shv[c + 3]), 0.f) * wv[c + 3];
    }
    out[r] = s + b3[0];
}

// ---------------------------------------------------------------------------
extern "C" void kernel_launch(void* const* d_in, const int* in_sizes, int n_in,
                              void* d_out, int out_size) {
    const float* x   = (const float*)d_in[0];
    const int*   ei  = (const int*)d_in[1];
    const float* Wl1 = (const float*)d_in[2];
    const float* bl1 = (const float*)d_in[3];
    const float* Wr1 = (const float*)d_in[4];
    const float* Wl2 = (const float*)d_in[5];
    const float* bl2 = (const float*)d_in[6];
    const float* Wr2 = (const float*)d_in[7];
    const float* W1  = (const float*)d_in[8];
    const float* b1  = (const float*)d_in[9];
    const float* g1  = (const float*)d_in[10];
    const float* be1 = (const float*)d_in[11];
    const float* W2  = (const float*)d_in[12];
    const float* b2  = (const float*)d_in[13];
    const float* g2  = (const float*)d_in[14];
    const float* be2 = (const float*)d_in[15];
    const float* W3  = (const float*)d_in[16];
    const float* b3  = (const float*)d_in[17];

    const int N = in_sizes[0] / F_IN;
    const int E = in_sizes[1] / 2;
    const int* src = ei;
    const int* dst = ei + E;

    float* out = (float*)d_out;
    float* h1  = out + N;
    float* h2  = h1 + (size_t)N * HID;

    float* base = nullptr;
    cudaGetSymbolAddress((void**)&base, g_scratch);
    float* invdeg = base;
    float* agg    = invdeg + NMAX;
    float* t1     = agg + (size_t)NMAX * 128;
    float* t2     = t1 + (size_t)NMAX * 128;
    float* sum1   = t2 + (size_t)NMAX * 64;
    float* sumsq1 = sum1 + 128;
    float* sum2   = sumsq1 + 128;
    float* sumsq2 = sum2 + 64;
    float* sc1    = sumsq2 + 64;
    float* sh1    = sc1 + 128;
    float* sc2    = sh1 + 128;
    float* sh2    = sc2 + 64;

    int *deg = nullptr, *off = nullptr, *cur = nullptr, *csr = nullptr;
    int *bsum = nullptr, *boff = nullptr;
    cudaGetSymbolAddress((void**)&deg, g_deg);
    cudaGetSymbolAddress((void**)&off, g_off);
    cudaGetSymbolAddress((void**)&cur, g_cur);
    cudaGetSymbolAddress((void**)&csr, g_csr);
    cudaGetSymbolAddress((void**)&bsum, g_bsum);
    cudaGetSymbolAddress((void**)&boff, g_boff);
    __nv_bfloat16 *wh = nullptr, *wl = nullptr;
    cudaGetSymbolAddress((void**)&wh, g_wh);
    cudaGetSymbolAddress((void**)&wl, g_wl);

    const int TB = 256;
    const int gemm_grid = (N + 63) / 64;      // BM=64 tiles
    const int gather_grid = (N * 32 + TB - 1) / TB;
    const int scan_blocks = (N + 255) / 256;  // 196 <= 256

    // prep + init
    prep_weights<<<(WTOTAL + TB - 1) / TB, TB>>>(Wl1, Wr1, Wl2, Wr2, W1, W2, wh, wl);
    zero_kernel<<<(N + TB - 1) / TB, TB>>>(deg, N);

    // CSR build: deg -> 3-phase parallel scan -> fill
    deg_kernel<<<(E + TB - 1) / TB, TB>>>(dst, deg, E);
    block_sums<<<scan_blocks, 256>>>(deg, bsum, N);
    scan_partials<<<1, 256>>>(bsum, boff, scan_blocks, sum1);
    offsets_kernel<<<scan_blocks, 256>>>(deg, boff, off, cur, invdeg, N, E);
    fill_kernel<<<(E + TB - 1) / TB, TB>>>(src, dst, cur, csr, E);

    // SAGE layer 1
    gather_agg<F_IN / 4><<<gather_grid, TB>>>((const float4*)x, csr, off, invdeg,
                                              (float4*)agg, N);
    mma_gemm<100, 112, 100, 112, 128, true, false, false><<<gemm_grid, TB>>>(
        agg, x, wh + WOFF_L1, wl + WOFF_L1, wh + WOFF_R1, wl + WOFF_R1,
        bl1, nullptr, nullptr, nullptr, nullptr, h1, N);

    // SAGE layer 2
    gather_agg<HID / 4><<<gather_grid, TB>>>((const float4*)h1, csr, off, invdeg,
                                             (float4*)agg, N);
    mma_gemm<128, 128, 128, 128, 128, true, false, false><<<gemm_grid, TB>>>(
        agg, h1, wh + WOFF_L2, wl + WOFF_L2, wh + WOFF_R2, wl + WOFF_R2,
        bl2, nullptr, nullptr, nullptr, nullptr, h2, N);

    // MLP layer 1: t1 = h2@W1 + b1 (+stats)
    mma_gemm<128, 128, 0, 0, 128, false, false, true><<<gemm_grid, TB>>>(
        h2, h2, wh + WOFF_M1, wl + WOFF_M1, wh + WOFF_M1, wl + WOFF_M1,
        b1, nullptr, nullptr, sum1, sumsq1, t1, N);
    bn_finalize_kernel<<<1, 128>>>(sum1, sumsq1, g1, be1, sc1, sh1, 128, 1.0f / (float)N);

    // MLP layer 2: t2 = relu(bn(t1))@W2 + b2 (BN+relu fused into A load, +stats)
    mma_gemm<128, 128, 0, 0, 64, false, true, true><<<gemm_grid, TB>>>(
        t1, t1, wh + WOFF_M2, wl + WOFF_M2, wh + WOFF_M2, wl + WOFF_M2,
        b2, sc1, sh1, sum2, sumsq2, t2, N);
    bn_finalize_kernel<<<1, 64>>>(sum2, sumsq2, g2, be2, sc2, sh2, 64, 1.0f / (float)N);

    // final
    final_kernel<<<(N + TB - 1) / TB, TB>>>(t2, sc2, sh2, W3, b3, out, N);
}

// round 14
// speedup vs baseline: 1.0009x; 1.0009x over previous
#include <cuda_runtime.h>
#include <cuda_bf16.h>
#include <cstdint>

#define NMAX 50000
#define EMAX 800000
#define F_IN 100
#define HID  128
#define H2D  64

// ---- scratch ----
__device__ int   g_deg[NMAX];
__device__ int   g_off[NMAX + 1];
__device__ int   g_cur[NMAX];
__device__ int   g_csr[EMAX];
__device__ int   g_bsum[256];
__device__ int   g_boff[256];
// invdeg | agg[N*128] | t1[N*128] | t2[N*64] | bn(768)
__device__ float g_scratch[NMAX * 321 + 768];

// split weights bf16 hi/lo, transposed [NC][Kpad]
#define WOFF_L1  0
#define WOFF_R1  14336
#define WOFF_L2  28672
#define WOFF_R2  45056
#define WOFF_M1  61440
#define WOFF_M2  77824
#define WTOTAL   86016
__device__ __nv_bfloat16 g_wh[WTOTAL];
__device__ __nv_bfloat16 g_wl[WTOTAL];

// ---------------------------------------------------------------------------
__global__ void zero_kernel(int* __restrict__ p, int n) {
    int i = blockIdx.x * blockDim.x + threadIdx.x;
    for (; i < n; i += gridDim.x * blockDim.x) p[i] = 0;
}

__global__ void deg_kernel(const int* __restrict__ dst, int* __restrict__ deg, int E) {
    int e = blockIdx.x * blockDim.x + threadIdx.x;
    if (e < E) atomicAdd(&deg[dst[e]], 1);
}

// ---- three-phase parallel exclusive scan ----
__global__ void block_sums(const int* __restrict__ deg, int* __restrict__ bsum, int N) {
    int i = blockIdx.x * 256 + threadIdx.x;
    int lane = threadIdx.x & 31, w = threadIdx.x >> 5;
    int v = (i < N) ? deg[i] : 0;
#pragma unroll
    for (int o = 16; o; o >>= 1) v += __shfl_down_sync(~0u, v, o);
    __shared__ int ws[8];
    if (lane == 0) ws[w] = v;
    __syncthreads();
    if (threadIdx.x == 0) {
        int s = 0;
#pragma unroll
        for (int j = 0; j < 8; j++) s += ws[j];
        bsum[blockIdx.x] = s;
    }
}

// 1 block, 256 threads; exclusive-scans nb (<=256) partials; zeroes BN sums
__global__ void scan_partials(const int* __restrict__ bsum, int* __restrict__ boff,
                              int nb, float* __restrict__ bnzero) {
    int t = threadIdx.x, lane = t & 31, w = t >> 5;
    for (int i = t; i < 384; i += 256) bnzero[i] = 0.f;
    int d = (t < nb) ? bsum[t] : 0;
    int v = d;
#pragma unroll
    for (int o = 1; o < 32; o <<= 1) {
        int u = __shfl_up_sync(~0u, v, o);
        if (lane >= o) v += u;
    }
    __shared__ int ws[8];
    if (lane == 31) ws[w] = v;
    __syncthreads();
    int add = 0;
#pragma unroll
    for (int j = 0; j < 8; j++) if (j < w) add += ws[j];
    boff[t] = v - d + add;
}

__global__ void offsets_kernel(const int* __restrict__ deg, const int* __restrict__ boff,
                               int* __restrict__ off, int* __restrict__ cur,
                               float* __restrict__ invdeg, int N, int E) {
    int i = blockIdx.x * 256 + threadIdx.x;
    int t = threadIdx.x, lane = t & 31, w = t >> 5;
    int d = (i < N) ? deg[i] : 0;
    int v = d;
#pragma unroll
    for (int o = 1; o < 32; o <<= 1) {
        int u = __shfl_up_sync(~0u, v, o);
        if (lane >= o) v += u;
    }
    __shared__ int ws[8];
    if (lane == 31) ws[w] = v;
    __syncthreads();
    int add = 0;
#pragma unroll
    for (int j = 0; j < 8; j++) if (j < w) add += ws[j];
    int excl = v - d + add + boff[blockIdx.x];
    if (i < N) {
        off[i] = excl;
        cur[i] = excl;
        invdeg[i] = 1.0f / fmaxf((float)d, 1.0f);
    }
    if (i == 0) off[N] = E;
}

__global__ void fill_kernel(const int* __restrict__ src, const int* __restrict__ dst,
                            int* __restrict__ cur, int* __restrict__ csr, int E) {
    int e = blockIdx.x * blockDim.x + threadIdx.x;
    if (e < E) {
        int pos = atomicAdd(&cur[dst[e]], 1);
        csr[pos] = src[e];
    }
}

// split + transpose all 6 weight matrices into bf16 hi/lo, [NC][Kpad]
__global__ void prep_weights(const float* __restrict__ Wl1, const float* __restrict__ Wr1,
                             const float* __restrict__ Wl2, const float* __restrict__ Wr2,
                             const float* __restrict__ W1,  const float* __restrict__ W2,
                             __nv_bfloat16* __restrict__ wh, __nv_bfloat16* __restrict__ wl) {
    int i = blockIdx.x * blockDim.x + threadIdx.x;
    if (i >= WTOTAL) return;
    const float* W; int K, KP, NC, local;
    if (i < WOFF_L2) {
        if (i < WOFF_R1) { W = Wl1; local = i; }
        else             { W = Wr1; local = i - WOFF_R1; }
        K = 100; KP = 112; NC = 128;
    } else if (i < WOFF_M2) {
        if (i < WOFF_R2)      { W = Wl2; local = i - WOFF_L2; }
        else if (i < WOFF_M1) { W = Wr2; local = i - WOFF_R2; }
        else                  { W = W1;  local = i - WOFF_M1; }
        K = 128; KP = 128; NC = 128;
    } else {
        W = W2; local = i - WOFF_M2; K = 128; KP = 128; NC = 64;
    }
    int n = local / KP, k = local - n * KP;
    float v = (k < K) ? W[k * NC + n] : 0.f;
    __nv_bfloat16 h = __float2bfloat16_rn(v);
    wh[i] = h;
    wl[i] = __float2bfloat16_rn(v - __bfloat162float(h));
}

// ---------------------------------------------------------------------------
// gather aggregation: warp per dst node, lane owns one float4 feature group.
// ---------------------------------------------------------------------------
template <int F4>
__global__ void gather_agg(const float4* __restrict__ x4, const int* __restrict__ csr,
                           const int* __restrict__ off, const float* __restrict__ invdeg,
                           float4* __restrict__ agg, int N) {
    int w = (blockIdx.x * blockDim.x + threadIdx.x) >> 5;
    int lane = threadIdx.x & 31;
    if (w >= N || lane >= F4) return;
    int o = off[w];
    int d = off[w + 1] - o;
    float4 acc = make_float4(0.f, 0.f, 0.f, 0.f);
    int j = 0;
    for (; j + 2 <= d; j += 2) {
        int s0 = __ldg(&csr[o + j]);
        int s1 = __ldg(&csr[o + j + 1]);
        float4 v0 = __ldg(&x4[(size_t)s0 * F4 + lane]);
        float4 v1 = __ldg(&x4[(size_t)s1 * F4 + lane]);
        acc.x += v0.x; acc.y += v0.y; acc.z += v0.z; acc.w += v0.w;
        acc.x += v1.x; acc.y += v1.y; acc.z += v1.z; acc.w += v1.w;
    }
    if (j < d) {
        int s0 = __ldg(&csr[o + j]);
        float4 v0 = __ldg(&x4[(size_t)s0 * F4 + lane]);
        acc.x += v0.x; acc.y += v0.y; acc.z += v0.z; acc.w += v0.w;
    }
    float iv = invdeg[w];
    agg[(size_t)w * F4 + lane] = make_float4(acc.x * iv, acc.y * iv, acc.z * iv, acc.w * iv);
}

// ---------------------------------------------------------------------------
// Tensor-core GEMM, two-term bf16 split (3 MMAs), ldmatrix frags,
// double-buffered smem, cp.async for B tiles. BM=64 tiles for occupancy 3.
// ---------------------------------------------------------------------------
__device__ __forceinline__ uint32_t smem_u32(const void* p) {
    return (uint32_t)__cvta_generic_to_shared(p);
}

#define LDSM4(R, a)                                                             \
    asm volatile("ldmatrix.sync.aligned.m8n8.x4.shared.b16 {%0,%1,%2,%3}, [%4];"\
                 : "=r"((R)[0]), "=r"((R)[1]), "=r"((R)[2]), "=r"((R)[3])       \
                 : "r"(a))

#define MMA16816(C, A, b0, b1)                                                  \
    asm volatile("mma.sync.aligned.m16n8k16.row.col.f32.bf16.bf16.f32 "         \
                 "{%0,%1,%2,%3}, {%4,%5,%6,%7}, {%8,%9}, {%0,%1,%2,%3};"        \
                 : "+f"((C)[0]), "+f"((C)[1]), "+f"((C)[2]), "+f"((C)[3])       \
                 : "r"((A)[0]), "r"((A)[1]), "r"((A)[2]), "r"((A)[3]),          \
                   "r"(b0), "r"(b1))

#define CP_ASYNC16(smem_addr, gptr)                                             \
    asm volatile("cp.async.ca.shared.global [%0], [%1], 16;"                    \
                 :: "r"(smem_addr), "l"(gptr) : "memory")

template <int K1, int KP1, int K2, int KP2, int NC, bool RELU, bool BNRELU, bool STATS>
__global__ __launch_bounds__(256, 3) void mma_gemm(
    const float* __restrict__ A1, const float* __restrict__ A2,
    const __nv_bfloat16* __restrict__ B1h, const __nv_bfloat16* __restrict__ B1l,
    const __nv_bfloat16* __restrict__ B2h, const __nv_bfloat16* __restrict__ B2l,
    const float* __restrict__ bias,
    const float* __restrict__ bnsc, const float* __restrict__ bnsh,
    float* __restrict__ gsum, float* __restrict__ gsumsq,
    float* __restrict__ out, int N) {

    // BM = 64. 8 warps: 4 along M (16 rows each), 2 along N.
    constexpr int NCW = NC / 2;            // 64 or 32 cols per warp
    constexpr int NT = NCW / 8;            // 8 or 4
    constexpr int NH = NCW / 32;           // 2 or 1 (16-col ldsm pairs per half)
    constexpr int C1 = KP1 / 16, C2 = KP2 / 16, NCH = C1 + C2;
    constexpr int BCP = NC * 2;            // 16B chunks per B array per stage

    __shared__ __align__(16) __nv_bfloat16 Ah[2][64][24], Al[2][64][24];
    __shared__ __align__(16) __nv_bfloat16 Bh[2][NC][24],  Bl[2][NC][24];

    const int tid = threadIdx.x, lane = tid & 31, wid = tid >> 5;
    const int wm = wid >> 1, wn = wid & 1;
    const int row0 = blockIdx.x * 64;

    float acc[NT][4];
#pragma unroll
    for (int nt = 0; nt < NT; nt++)
#pragma unroll
        for (int q = 0; q < 4; q++) acc[nt][q] = 0.f;

    float2 av[2];                 // A staging (fp32 -> bf16 split conversion)
    const int kk2 = (tid & 7) * 2;
    const int mr  = tid >> 3;     // 0..31

    auto issue_B = [&](int ch, int st) {
        const __nv_bfloat16 *gh, *gl; int KPE, k0;
        if (ch < C1) { gh = B1h; gl = B1l; KPE = KP1; k0 = ch * 16; }
        else         { gh = B2h; gl = B2l; KPE = KP2; k0 = (ch - C1) * 16; }
#pragma unroll
        for (int j = 0; j < (BCP + 255) / 256; j++) {
            int w = tid + j * 256;
            if (BCP < 256 && w >= BCP) break;
            int n = w >> 1, half = w & 1;
            const __nv_bfloat16* srch = gh + n * KPE + k0 + half * 8;
            const __nv_bfloat16* srcl = gl + n * KPE + k0 + half * 8;
            CP_ASYNC16(smem_u32(&Bh[st][n][half * 8]), srch);
            CP_ASYNC16(smem_u32(&Bl[st][n][half * 8]), srcl);
        }
        asm volatile("cp.async.commit_group;" ::: "memory");
    };

    auto load_A = [&](int ch) {
        const float* A; int K, k0; bool bn;
        if (ch < C1) { A = A1; K = K1; k0 = ch * 16; bn = BNRELU; }
        else         { A = A2; K = K2; k0 = (ch - C1) * 16; bn = false; }
        const int kt = k0 + kk2;
        float s0 = 1.f, h0 = 0.f, s1 = 1.f, h1 = 0.f;
        if (BNRELU && bn) {
            if (kt < K)     { s0 = bnsc[kt];     h0 = bnsh[kt]; }
            if (kt + 1 < K) { s1 = bnsc[kt + 1]; h1 = bnsh[kt + 1]; }
        }
#pragma unroll
        for (int i = 0; i < 2; i++) {
            int row = row0 + mr + i * 32;
            float v0 = 0.f, v1 = 0.f;
            if (row < N) {
                const float* ar = A + (size_t)row * K;
                if (kt + 1 < K) { float2 tv = *(const float2*)(ar + kt); v0 = tv.x; v1 = tv.y; }
                else if (kt < K) { v0 = ar[kt]; }
            }
            if (BNRELU && bn) {
                v0 = fmaxf(fmaf(v0, s0, h0), 0.f);
                v1 = fmaxf(fmaf(v1, s1, h1), 0.f);
            }
            av[i] = make_float2(v0, v1);
        }
    };

    auto store_A = [&](int st) {
#pragma unroll
        for (int i = 0; i < 2; i++) {
            int m = mr + i * 32;
            float2 v = av[i];
            __nv_bfloat162 h2 = __float22bfloat162_rn(v);
            float2 hf = __bfloat1622float2(h2);
            __nv_bfloat162 l2 = __float22bfloat162_rn(make_float2(v.x - hf.x, v.y - hf.y));
            *(uint32_t*)&Ah[st][m][kk2] = *(uint32_t*)&h2;
            *(uint32_t*)&Al[st][m][kk2] = *(uint32_t*)&l2;
        }
    };

    const int arow = (lane & 15), acol = ((lane >> 4) << 3);
    const int brow = (lane & 7) + ((lane & 16) >> 1), bcol = (lane & 8);

    // prologue: fill stage 0
    issue_B(0, 0);
    load_A(0);
    store_A(0);
    asm volatile("cp.async.wait_group 0;" ::: "memory");
    __syncthreads();

    for (int ch = 0; ch < NCH; ch++) {
        const int st = ch & 1;
        if (ch + 1 < NCH) {
            issue_B(ch + 1, st ^ 1);  // async, lands during MMAs
            load_A(ch + 1);           // global loads in flight during MMAs
        }

        uint32_t fah[4], fal[4];
        {
            int m0 = wm * 16;
            LDSM4(fah, smem_u32(&Ah[st][m0 + arow][acol]));
            LDSM4(fal, smem_u32(&Al[st][m0 + arow][acol]));
        }
#pragma unroll
        for (int nh = 0; nh < NH; nh++) {
#pragma unroll
            for (int p = 0; p < 2; p++) {
                uint32_t fbh[4], fbl[4];
                int n0 = wn * NCW + (nh * 2 + p) * 16;
                LDSM4(fbh, smem_u32(&Bh[st][n0 + brow][bcol]));
                LDSM4(fbl, smem_u32(&Bl[st][n0 + brow][bcol]));
#pragma unroll
                for (int hh = 0; hh < 2; hh++) {
                    int nt = nh * 4 + p * 2 + hh;
                    MMA16816(acc[nt], fah, fbh[2 * hh], fbh[2 * hh + 1]);
                    MMA16816(acc[nt], fah, fbl[2 * hh], fbl[2 * hh + 1]);
                    MMA16816(acc[nt], fal, fbh[2 * hh], fbh[2 * hh + 1]);
                }
            }
        }
        if (ch + 1 < NCH) {
            store_A(st ^ 1);
            asm volatile("cp.async.wait_group 0;" ::: "memory");
        }
        __syncthreads();
    }

    // ---- epilogue ----
    const int g = lane >> 2, tg = lane & 3;
    float* s_st = reinterpret_cast<float*>(&Ah[0][0][0]);  // reuse smem
    if (STATS) {
        for (int i = tid; i < 2 * NC; i += 256) s_st[i] = 0.f;
        __syncthreads();
    }

    float ls[NT][2], lq[NT][2];
    if (STATS) {
#pragma unroll
        for (int nt = 0; nt < NT; nt++) { ls[nt][0] = ls[nt][1] = lq[nt][0] = lq[nt][1] = 0.f; }
    }

    {
        int rowA = row0 + wm * 16 + g;
        int rowB = rowA + 8;
#pragma unroll
        for (int nt = 0; nt < NT; nt++) {
            int col = wn * NCW + nt * 8 + tg * 2;
            float b0 = bias[col], b1 = bias[col + 1];
            float v0 = acc[nt][0] + b0, v1 = acc[nt][1] + b1;
            float v2 = acc[nt][2] + b0, v3 = acc[nt][3] + b1;
            if (RELU) {
                v0 = fmaxf(v0, 0.f); v1 = fmaxf(v1, 0.f);
                v2 = fmaxf(v2, 0.f); v3 = fmaxf(v3, 0.f);
            }
            if (rowA < N) {
                *(float2*)&out[(size_t)rowA * NC + col] = make_float2(v0, v1);
                if (STATS) {
                    ls[nt][0] += v0; lq[nt][0] += v0 * v0;
                    ls[nt][1] += v1; lq[nt][1] += v1 * v1;
                }
            }
            if (rowB < N) {
                *(float2*)&out[(size_t)rowB * NC + col] = make_float2(v2, v3);
                if (STATS) {
                    ls[nt][0] += v2; lq[nt][0] += v2 * v2;
                    ls[nt][1] += v3; lq[nt][1] += v3 * v3;
                }
            }
        }
    }

    if (STATS) {
#pragma unroll
        for (int nt = 0; nt < NT; nt++) {
            int col = wn * NCW + nt * 8 + tg * 2;
            atomicAdd(&s_st[col], ls[nt][0]);
            atomicAdd(&s_st[NC + col], lq[nt][0]);
            atomicAdd(&s_st[col + 1], ls[nt][1]);
            atomicAdd(&s_st[NC + col + 1], lq[nt][1]);
        }
        __syncthreads();
        for (int i = tid; i < NC; i += 256) {
            atomicAdd(&gsum[i], s_st[i]);
            atomicAdd(&gsumsq[i], s_st[NC + i]);
        }
    }
}

// ---------------------------------------------------------------------------
__global__ void bn_finalize_kernel(const float* __restrict__ gsum, const float* __restrict__ gsumsq,
                                   const float* __restrict__ gamma, const float* __restrict__ beta,
                                   float* __restrict__ sc, float* __restrict__ sh,
                                   int NC, float invN) {
    int c = threadIdx.x;
    if (c < NC) {
        float m = gsum[c] * invN;
        float var = gsumsq[c] * invN - m * m;
        float inv = rsqrtf(var + 1e-5f);
        float s = inv * gamma[c];
        sc[c] = s;
        sh[c] = beta[c] - m * s;
    }
}

__global__ void final_kernel(const float* __restrict__ t2,
                             const float* __restrict__ sc, const float* __restrict__ sh,
                             const float* __restrict__ W3, const float* __restrict__ b3,
                             float* __restrict__ out, int N) {
    __shared__ float wv[64], scv[64], shv[64];
    if (threadIdx.x < 64) {
        wv[threadIdx.x] = W3[threadIdx.x];
        scv[threadIdx.x] = sc[threadIdx.x];
        shv[threadIdx.x] = sh[threadIdx.x];
    }
    __syncthreads();
    int r = blockIdx.x * blockDim.x + threadIdx.x;
    if (r >= N) return;
    const float4* row = (const float4*)(t2 + (size_t)r * 64);
    float s = 0.f;
#pragma unroll
    for (int q = 0; q < 16; q++) {
        float4 v = row[q];
        int c = q * 4;
        s += fmaxf(fmaf(v.x, scv[c + 0], shv[c + 0]), 0.f) * wv[c + 0];
        s += fmaxf(fmaf(v.y, scv[c + 1], shv[c + 1]), 0.f) * wv[c + 1];
        s += fmaxf(fmaf(v.z, scv[c + 2], shv[c + 2]), 0.f) * wv[c + 2];
        s += fmaxf(fmaf(v.w, scv[c + 3], shv[c + 3]), 0.f) * wv[c + 3];
    }
    out[r] = s + b3[0];
}

// ---------------------------------------------------------------------------
extern "C" void kernel_launch(void* const* d_in, const int* in_sizes, int n_in,
                              void* d_out, int out_size) {
    const float* x   = (const float*)d_in[0];
    const int*   ei  = (const int*)d_in[1];
    const float* Wl1 = (const float*)d_in[2];
    const float* bl1 = (const float*)d_in[3];
    const float* Wr1 = (const float*)d_in[4];
    const float* Wl2 = (const float*)d_in[5];
    const float* bl2 = (const float*)d_in[6];
    const float* Wr2 = (const float*)d_in[7];
    const float* W1  = (const float*)d_in[8];
    const float* b1  = (const float*)d_in[9];
    const float* g1  = (const float*)d_in[10];
    const float* be1 = (const float*)d_in[11];
    const float* W2  = (const float*)d_in[12];
    const float* b2  = (const float*)d_in[13];
    const float* g2  = (const float*)d_in[14];
    const float* be2 = (const float*)d_in[15];
    const float* W3  = (const float*)d_in[16];
    const float* b3  = (const float*)d_in[17];

    const int N = in_sizes[0] / F_IN;
    const int E = in_sizes[1] / 2;
    const int* src = ei;
    const int* dst = ei + E;

    float* out = (float*)d_out;
    float* h1  = out + N;
    float* h2  = h1 + (size_t)N * HID;

    float* base = nullptr;
    cudaGetSymbolAddress((void**)&base, g_scratch);
    float* invdeg = base;
    float* agg    = invdeg + NMAX;
    float* t1     = agg + (size_t)NMAX * 128;
    float* t2     = t1 + (size_t)NMAX * 128;
    float* sum1   = t2 + (size_t)NMAX * 64;
    float* sumsq1 = sum1 + 128;
    float* sum2   = sumsq1 + 128;
    float* sumsq2 = sum2 + 64;
    float* sc1    = sumsq2 + 64;
    float* sh1    = sc1 + 128;
    float* sc2    = sh1 + 128;
    float* sh2    = sc2 + 64;

    int *deg = nullptr, *off = nullptr, *cur = nullptr, *csr = nullptr;
    int *bsum = nullptr, *boff = nullptr;
    cudaGetSymbolAddress((void**)&deg, g_deg);
    cudaGetSymbolAddress((void**)&off, g_off);
    cudaGetSymbolAddress((void**)&cur, g_cur);
    cudaGetSymbolAddress((void**)&csr, g_csr);
    cudaGetSymbolAddress((void**)&bsum, g_bsum);
    cudaGetSymbolAddress((void**)&boff, g_boff);
    __nv_bfloat16 *wh = nullptr, *wl = nullptr;
    cudaGetSymbolAddress((void**)&wh, g_wh);
    cudaGetSymbolAddress((void**)&wl, g_wl);

    const int TB = 256;
    const int gemm_grid = (N + 63) / 64;      // BM=64 tiles
    const int gather_grid = (N * 32 + TB - 1) / TB;
    const int scan_blocks = (N + 255) / 256;  // 196 <= 256

    // prep + init
    prep_weights<<<(WTOTAL + TB - 1) / TB, TB>>>(Wl1, Wr1, Wl2, Wr2, W1, W2, wh, wl);
    zero_kernel<<<(N + TB - 1) / TB, TB>>>(deg, N);

    // CSR build: deg -> 3-phase parallel scan -> fill
    deg_kernel<<<(E + TB - 1) / TB, TB>>>(dst, deg, E);
    block_sums<<<scan_blocks, 256>>>(deg, bsum, N);
    scan_partials<<<1, 256>>>(bsum, boff, scan_blocks, sum1);
    offsets_kernel<<<scan_blocks, 256>>>(deg, boff, off, cur, invdeg, N, E);
    fill_kernel<<<(E + TB - 1) / TB, TB>>>(src, dst, cur, csr, E);

    // SAGE layer 1
    gather_agg<F_IN / 4><<<gather_grid, TB>>>((const float4*)x, csr, off, invdeg,
                                              (float4*)agg, N);
    mma_gemm<100, 112, 100, 112, 128, true, false, false><<<gemm_grid, TB>>>(
        agg, x, wh + WOFF_L1, wl + WOFF_L1, wh + WOFF_R1, wl + WOFF_R1,
        bl1, nullptr, nullptr, nullptr, nullptr, h1, N);

    // SAGE layer 2
    gather_agg<HID / 4><<<gather_grid, TB>>>((const float4*)h1, csr, off, invdeg,
                                             (float4*)agg, N);
    mma_gemm<128, 128, 128, 128, 128, true, false, false><<<gemm_grid, TB>>>(
        agg, h1, wh + WOFF_L2, wl + WOFF_L2, wh + WOFF_R2, wl + WOFF_R2,
        bl2, nullptr, nullptr, nullptr, nullptr, h2, N);

    // MLP layer 1: t1 = h2@W1 + b1 (+stats)
    mma_gemm<128, 128, 0, 0, 128, false, false, true><<<gemm_grid, TB>>>(
        h2, h2, wh + WOFF_M1, wl + WOFF_M1, wh + WOFF_M1, wl + WOFF_M1,
        b1, nullptr, nullptr, sum1, sumsq1, t1, N);
    bn_finalize_kernel<<<1, 128>>>(sum1, sumsq1, g1, be1, sc1, sh1, 128, 1.0f / (float)N);

    // MLP layer 2: t2 = relu(bn(t1))@W2 + b2 (BN+relu fused into A load, +stats)
    mma_gemm<128, 128, 0, 0, 64, false, true, true><<<gemm_grid, TB>>>(
        t1, t1, wh + WOFF_M2, wl + WOFF_M2, wh + WOFF_M2, wl + WOFF_M2,
        b2, sc1, sh1, sum2, sumsq2, t2, N);
    bn_finalize_kernel<<<1, 64>>>(sum2, sumsq2, g2, be2, sc2, sh2, 64, 1.0f / (float)N);

    // final
    final_kernel<<<(N + TB - 1) / TB, TB>>>(t2, sc2, sh2, W3, b3, out, N);
}

// round 15
// speedup vs baseline: 1.0020x; 1.0011x over previous
#include <cuda_runtime.h>
#include <cuda_bf16.h>
#include <cstdint>

#define NMAX 50000
#define EMAX 800000
#define F_IN 100
#define HID  128
#define H2D  64

// ---- scratch ----
__device__ int   g_deg[NMAX];
__device__ int   g_off[NMAX + 1];
__device__ int   g_cur[NMAX];
__device__ int   g_csr[EMAX];
__device__ int   g_bsum[256];
__device__ int   g_boff[256];
// invdeg | agg[N*128] | t1[N*128] | t2[N*64] | bn(768)
__device__ float g_scratch[NMAX * 321 + 768];

// split weights bf16 hi/lo, transposed [NC][Kpad]
#define WOFF_L1  0
#define WOFF_R1  14336
#define WOFF_L2  28672
#define WOFF_R2  45056
#define WOFF_M1  61440
#define WOFF_M2  77824
#define WTOTAL   86016
__device__ __nv_bfloat16 g_wh[WTOTAL];
__device__ __nv_bfloat16 g_wl[WTOTAL];

// ---------------------------------------------------------------------------
__global__ void zero_kernel(int* __restrict__ p, int n) {
    int i = blockIdx.x * blockDim.x + threadIdx.x;
    for (; i < n; i += gridDim.x * blockDim.x) p[i] = 0;
}

__global__ void deg_kernel(const int* __restrict__ dst, int* __restrict__ deg, int E) {
    int e = blockIdx.x * blockDim.x + threadIdx.x;
    if (e < E) atomicAdd(&deg[dst[e]], 1);
}

// ---- three-phase parallel exclusive scan ----
__global__ void block_sums(const int* __restrict__ deg, int* __restrict__ bsum, int N) {
    int i = blockIdx.x * 256 + threadIdx.x;
    int lane = threadIdx.x & 31, w = threadIdx.x >> 5;
    int v = (i < N) ? deg[i] : 0;
#pragma unroll
    for (int o = 16; o; o >>= 1) v += __shfl_down_sync(~0u, v, o);
    __shared__ int ws[8];
    if (lane == 0) ws[w] = v;
    __syncthreads();
    if (threadIdx.x == 0) {
        int s = 0;
#pragma unroll
        for (int j = 0; j < 8; j++) s += ws[j];
        bsum[blockIdx.x] = s;
    }
}

// 1 block, 256 threads; exclusive-scans nb (<=256) partials; zeroes BN sums
__global__ void scan_partials(const int* __restrict__ bsum, int* __restrict__ boff,
                              int nb, float* __restrict__ bnzero) {
    int t = threadIdx.x, lane = t & 31, w = t >> 5;
    for (int i = t; i < 384; i += 256) bnzero[i] = 0.f;
    int d = (t < nb) ? bsum[t] : 0;
    int v = d;
#pragma unroll
    for (int o = 1; o < 32; o <<= 1) {
        int u = __shfl_up_sync(~0u, v, o);
        if (lane >= o) v += u;
    }
    __shared__ int ws[8];
    if (lane == 31) ws[w] = v;
    __syncthreads();
    int add = 0;
#pragma unroll
    for (int j = 0; j < 8; j++) if (j < w) add += ws[j];
    boff[t] = v - d + add;
}

__global__ void offsets_kernel(const int* __restrict__ deg, const int* __restrict__ boff,
                               int* __restrict__ off, int* __restrict__ cur,
                               float* __restrict__ invdeg, int N, int E) {
    int i = blockIdx.x * 256 + threadIdx.x;
    int t = threadIdx.x, lane = t & 31, w = t >> 5;
    int d = (i < N) ? deg[i] : 0;
    int v = d;
#pragma unroll
    for (int o = 1; o < 32; o <<= 1) {
        int u = __shfl_up_sync(~0u, v, o);
        if (lane >= o) v += u;
    }
    __shared__ int ws[8];
    if (lane == 31) ws[w] = v;
    __syncthreads();
    int add = 0;
#pragma unroll
    for (int j = 0; j < 8; j++) if (j < w) add += ws[j];
    int excl = v - d + add + boff[blockIdx.x];
    if (i < N) {
        off[i] = excl;
        cur[i] = excl;
        invdeg[i] = 1.0f / fmaxf((float)d, 1.0f);
    }
    if (i == 0) off[N] = E;
}

__global__ void fill_kernel(const int* __restrict__ src, const int* __restrict__ dst,
                            int* __restrict__ cur, int* __restrict__ csr, int E) {
    int e = blockIdx.x * blockDim.x + threadIdx.x;
    if (e < E) {
        int pos = atomicAdd(&cur[dst[e]], 1);
        csr[pos] = src[e];
    }
}

// split + transpose all 6 weight matrices into bf16 hi/lo, [NC][Kpad]
__global__ void prep_weights(const float* __restrict__ Wl1, const float* __restrict__ Wr1,
                             const float* __restrict__ Wl2, const float* __restrict__ Wr2,
                             const float* __restrict__ W1,  const float* __restrict__ W2,
                             __nv_bfloat16* __restrict__ wh, __nv_bfloat16* __restrict__ wl) {
    int i = blockIdx.x * blockDim.x + threadIdx.x;
    if (i >= WTOTAL) return;
    const float* W; int K, KP, NC, local;
    if (i < WOFF_L2) {
        if (i < WOFF_R1) { W = Wl1; local = i; }
        else             { W = Wr1; local = i - WOFF_R1; }
        K = 100; KP = 112; NC = 128;
    } else if (i < WOFF_M2) {
        if (i < WOFF_R2)      { W = Wl2; local = i - WOFF_L2; }
        else if (i < WOFF_M1) { W = Wr2; local = i - WOFF_R2; }
        else                  { W = W1;  local = i - WOFF_M1; }
        K = 128; KP = 128; NC = 128;
    } else {
        W = W2; local = i - WOFF_M2; K = 128; KP = 128; NC = 64;
    }
    int n = local / KP, k = local - n * KP;
    float v = (k < K) ? W[k * NC + n] : 0.f;
    __nv_bfloat16 h = __float2bfloat16_rn(v);
    wh[i] = h;
    wl[i] = __float2bfloat16_rn(v - __bfloat162float(h));
}

// ---------------------------------------------------------------------------
// gather aggregation: warp per dst node, lane owns one float4 feature group.
// ---------------------------------------------------------------------------
template <int F4>
__global__ void gather_agg(const float4* __restrict__ x4, const int* __restrict__ csr,
                           const int* __restrict__ off, const float* __restrict__ invdeg,
                           float4* __restrict__ agg, int N) {
    int w = (blockIdx.x * blockDim.x + threadIdx.x) >> 5;
    int lane = threadIdx.x & 31;
    if (w >= N || lane >= F4) return;
    int o = off[w];
    int d = off[w + 1] - o;
    float4 acc = make_float4(0.f, 0.f, 0.f, 0.f);
    int j = 0;
    for (; j + 2 <= d; j += 2) {
        int s0 = __ldg(&csr[o + j]);
        int s1 = __ldg(&csr[o + j + 1]);
        float4 v0 = __ldg(&x4[(size_t)s0 * F4 + lane]);
        float4 v1 = __ldg(&x4[(size_t)s1 * F4 + lane]);
        acc.x += v0.x; acc.y += v0.y; acc.z += v0.z; acc.w += v0.w;
        acc.x += v1.x; acc.y += v1.y; acc.z += v1.z; acc.w += v1.w;
    }
    if (j < d) {
        int s0 = __ldg(&csr[o + j]);
        float4 v0 = __ldg(&x4[(size_t)s0 * F4 + lane]);
        acc.x += v0.x; acc.y += v0.y; acc.z += v0.z; acc.w += v0.w;
    }
    float iv = invdeg[w];
    agg[(size_t)w * F4 + lane] = make_float4(acc.x * iv, acc.y * iv, acc.z * iv, acc.w * iv);
}

// ---------------------------------------------------------------------------
// Tensor-core GEMM, two-term bf16 split (3 MMAs), ldmatrix frags,
// double-buffered smem, cp.async for B tiles. BM=64 tiles for occupancy 3.
// ---------------------------------------------------------------------------
__device__ __forceinline__ uint32_t smem_u32(const void* p) {
    return (uint32_t)__cvta_generic_to_shared(p);
}

#define LDSM4(R, a)                                                             \
    asm volatile("ldmatrix.sync.aligned.m8n8.x4.shared.b16 {%0,%1,%2,%3}, [%4];"\
                 : "=r"((R)[0]), "=r"((R)[1]), "=r"((R)[2]), "=r"((R)[3])       \
                 : "r"(a))

#define MMA16816(C, A, b0, b1)                                                  \
    asm volatile("mma.sync.aligned.m16n8k16.row.col.f32.bf16.bf16.f32 "         \
                 "{%0,%1,%2,%3}, {%4,%5,%6,%7}, {%8,%9}, {%0,%1,%2,%3};"        \
                 : "+f"((C)[0]), "+f"((C)[1]), "+f"((C)[2]), "+f"((C)[3])       \
                 : "r"((A)[0]), "r"((A)[1]), "r"((A)[2]), "r"((A)[3]),          \
                   "r"(b0), "r"(b1))

#define CP_ASYNC16(smem_addr, gptr)                                             \
    asm volatile("cp.async.ca.shared.global [%0], [%1], 16;"                    \
                 :: "r"(smem_addr), "l"(gptr) : "memory")

template <int K1, int KP1, int K2, int KP2, int NC, bool RELU, bool BNRELU, bool STATS>
__global__ __launch_bounds__(256, 3) void mma_gemm(
    const float* __restrict__ A1, const float* __restrict__ A2,
    const __nv_bfloat16* __restrict__ B1h, const __nv_bfloat16* __restrict__ B1l,
    const __nv_bfloat16* __restrict__ B2h, const __nv_bfloat16* __restrict__ B2l,
    const float* __restrict__ bias,
    const float* __restrict__ bnsc, const float* __restrict__ bnsh,
    float* __restrict__ gsum, float* __restrict__ gsumsq,
    float* __restrict__ out, int N) {

    // BM = 64. 8 warps: 4 along M (16 rows each), 2 along N.
    constexpr int NCW = NC / 2;            // 64 or 32 cols per warp
    constexpr int NT = NCW / 8;            // 8 or 4
    constexpr int NH = NCW / 32;           // 2 or 1 (16-col ldsm pairs per half)
    constexpr int C1 = KP1 / 16, C2 = KP2 / 16, NCH = C1 + C2;
    constexpr int BCP = NC * 2;            // 16B chunks per B array per stage

    __shared__ __align__(16) __nv_bfloat16 Ah[2][64][24], Al[2][64][24];
    __shared__ __align__(16) __nv_bfloat16 Bh[2][NC][24],  Bl[2][NC][24];

    const int tid = threadIdx.x, lane = tid & 31, wid = tid >> 5;
    const int wm = wid >> 1, wn = wid & 1;
    const int row0 = blockIdx.x * 64;

    float acc[NT][4];
#pragma unroll
    for (int nt = 0; nt < NT; nt++)
#pragma unroll
        for (int q = 0; q < 4; q++) acc[nt][q] = 0.f;

    float2 av[2];                 // A staging (fp32 -> bf16 split conversion)
    const int kk2 = (tid & 7) * 2;
    const int mr  = tid >> 3;     // 0..31

    auto issue_B = [&](int ch, int st) {
        const __nv_bfloat16 *gh, *gl; int KPE, k0;
        if (ch < C1) { gh = B1h; gl = B1l; KPE = KP1; k0 = ch * 16; }
        else         { gh = B2h; gl = B2l; KPE = KP2; k0 = (ch - C1) * 16; }
#pragma unroll
        for (int j = 0; j < (BCP + 255) / 256; j++) {
            int w = tid + j * 256;
            if (BCP < 256 && w >= BCP) break;
            int n = w >> 1, half = w & 1;
            const __nv_bfloat16* srch = gh + n * KPE + k0 + half * 8;
            const __nv_bfloat16* srcl = gl + n * KPE + k0 + half * 8;
            CP_ASYNC16(smem_u32(&Bh[st][n][half * 8]), srch);
            CP_ASYNC16(smem_u32(&Bl[st][n][half * 8]), srcl);
        }
        asm volatile("cp.async.commit_group;" ::: "memory");
    };

    auto load_A = [&](int ch) {
        const float* A; int K, k0; bool bn;
        if (ch < C1) { A = A1; K = K1; k0 = ch * 16; bn = BNRELU; }
        else         { A = A2; K = K2; k0 = (ch - C1) * 16; bn = false; }
        const int kt = k0 + kk2;
        float s0 = 1.f, h0 = 0.f, s1 = 1.f, h1 = 0.f;
        if (BNRELU && bn) {
            if (kt < K)     { s0 = bnsc[kt];     h0 = bnsh[kt]; }
            if (kt + 1 < K) { s1 = bnsc[kt + 1]; h1 = bnsh[kt + 1]; }
        }
#pragma unroll
        for (int i = 0; i < 2; i++) {
            int row = row0 + mr + i * 32;
            float v0 = 0.f, v1 = 0.f;
            if (row < N) {
                const float* ar = A + (size_t)row * K;
                if (kt + 1 < K) { float2 tv = *(const float2*)(ar + kt); v0 = tv.x; v1 = tv.y; }
                else if (kt < K) { v0 = ar[kt]; }
            }
            if (BNRELU && bn) {
                v0 = fmaxf(fmaf(v0, s0, h0), 0.f);
                v1 = fmaxf(fmaf(v1, s1, h1), 0.f);
            }
            av[i] = make_float2(v0, v1);
        }
    };

    auto store_A = [&](int st) {
#pragma unroll
        for (int i = 0; i < 2; i++) {
            int m = mr + i * 32;
            float2 v = av[i];
            __nv_bfloat162 h2 = __float22bfloat162_rn(v);
            float2 hf = __bfloat1622float2(h2);
            __nv_bfloat162 l2 = __float22bfloat162_rn(make_float2(v.x - hf.x, v.y - hf.y));
            *(uint32_t*)&Ah[st][m][kk2] = *(uint32_t*)&h2;
            *(uint32_t*)&Al[st][m][kk2] = *(uint32_t*)&l2;
        }
    };

    const int arow = (lane & 15), acol = ((lane >> 4) << 3);
    const int brow = (lane & 7) + ((lane & 16) >> 1), bcol = (lane & 8);

    // prologue: fill stage 0
    issue_B(0, 0);
    load_A(0);
    store_A(0);
    asm volatile("cp.async.wait_group 0;" ::: "memory");
    __syncthreads();

    for (int ch = 0; ch < NCH; ch++) {
        const int st = ch & 1;
        if (ch + 1 < NCH) {
            issue_B(ch + 1, st ^ 1);  // async, lands during MMAs
            load_A(ch + 1);           // global loads in flight during MMAs
        }

        uint32_t fah[4], fal[4];
        {
            int m0 = wm * 16;
            LDSM4(fah, smem_u32(&Ah[st][m0 + arow][acol]));
            LDSM4(fal, smem_u32(&Al[st][m0 + arow][acol]));
        }
#pragma unroll
        for (int nh = 0; nh < NH; nh++) {
#pragma unroll
            for (int p = 0; p < 2; p++) {
                uint32_t fbh[4], fbl[4];
                int n0 = wn * NCW + (nh * 2 + p) * 16;
                LDSM4(fbh, smem_u32(&Bh[st][n0 + brow][bcol]));
                LDSM4(fbl, smem_u32(&Bl[st][n0 + brow][bcol]));
#pragma unroll
                for (int hh = 0; hh < 2; hh++) {
                    int nt = nh * 4 + p * 2 + hh;
                    MMA16816(acc[nt], fah, fbh[2 * hh], fbh[2 * hh + 1]);
                    MMA16816(acc[nt], fah, fbl[2 * hh], fbl[2 * hh + 1]);
                    MMA16816(acc[nt], fal, fbh[2 * hh], fbh[2 * hh + 1]);
                }
            }
        }
        if (ch + 1 < NCH) {
            store_A(st ^ 1);
            asm volatile("cp.async.wait_group 0;" ::: "memory");
        }
        __syncthreads();
    }

    // ---- epilogue ----
    const int g = lane >> 2, tg = lane & 3;
    float* s_st = reinterpret_cast<float*>(&Ah[0][0][0]);  // reuse smem
    if (STATS) {
        for (int i = tid; i < 2 * NC; i += 256) s_st[i] = 0.f;
        __syncthreads();
    }

    float ls[NT][2], lq[NT][2];
    if (STATS) {
#pragma unroll
        for (int nt = 0; nt < NT; nt++) { ls[nt][0] = ls[nt][1] = lq[nt][0] = lq[nt][1] = 0.f; }
    }

    {
        int rowA = row0 + wm * 16 + g;
        int rowB = rowA + 8;
#pragma unroll
        for (int nt = 0; nt < NT; nt++) {
            int col = wn * NCW + nt * 8 + tg * 2;
            float b0 = bias[col], b1 = bias[col + 1];
            float v0 = acc[nt][0] + b0, v1 = acc[nt][1] + b1;
            float v2 = acc[nt][2] + b0, v3 = acc[nt][3] + b1;
            if (RELU) {
                v0 = fmaxf(v0, 0.f); v1 = fmaxf(v1, 0.f);
                v2 = fmaxf(v2, 0.f); v3 = fmaxf(v3, 0.f);
            }
            if (rowA < N) {
                *(float2*)&out[(size_t)rowA * NC + col] = make_float2(v0, v1);
                if (STATS) {
                    ls[nt][0] += v0; lq[nt][0] += v0 * v0;
                    ls[nt][1] += v1; lq[nt][1] += v1 * v1;
                }
            }
            if (rowB < N) {
                *(float2*)&out[(size_t)rowB * NC + col] = make_float2(v2, v3);
                if (STATS) {
                    ls[nt][0] += v2; lq[nt][0] += v2 * v2;
                    ls[nt][1] += v3; lq[nt][1] += v3 * v3;
                }
            }
        }
    }

    if (STATS) {
#pragma unroll
        for (int nt = 0; nt < NT; nt++) {
            int col = wn * NCW + nt * 8 + tg * 2;
            atomicAdd(&s_st[col], ls[nt][0]);
            atomicAdd(&s_st[NC + col], lq[nt][0]);
            atomicAdd(&s_st[col + 1], ls[nt][1]);
            atomicAdd(&s_st[NC + col + 1], lq[nt][1]);
        }
        __syncthreads();
        for (int i = tid; i < NC; i += 256) {
            atomicAdd(&gsum[i], s_st[i]);
            atomicAdd(&gsumsq[i], s_st[NC + i]);
        }
    }
}

// ---------------------------------------------------------------------------
__global__ void bn_finalize_kernel(const float* __restrict__ gsum, const float* __restrict__ gsumsq,
                                   const float* __restrict__ gamma, const float* __restrict__ beta,
                                   float* __restrict__ sc, float* __restrict__ sh,
                                   int NC, float invN) {
    int c = threadIdx.x;
    if (c < NC) {
        float m = gsum[c] * invN;
        float var = gsumsq[c] * invN - m * m;
        float inv = rsqrtf(var + 1e-5f);
        float s = inv * gamma[c];
        sc[c] = s;
        sh[c] = beta[c] - m * s;
    }
}

__global__ void final_kernel(const float* __restrict__ t2,
                             const float* __restrict__ sc, const float* __restrict__ sh,
                             const float* __restrict__ W3, const float* __restrict__ b3,
                             float* __restrict__ out, int N) {
    __shared__ float wv[64], scv[64], shv[64];
    if (threadIdx.x < 64) {
        wv[threadIdx.x] = W3[threadIdx.x];
        scv[threadIdx.x] = sc[threadIdx.x];
        shv[threadIdx.x] = sh[threadIdx.x];
    }
    __syncthreads();
    int r = blockIdx.x * blockDim.x + threadIdx.x;
    if (r >= N) return;
    const float4* row = (const float4*)(t2 + (size_t)r * 64);
    float s = 0.f;
#pragma unroll
    for (int q = 0; q < 16; q++) {
        float4 v = row[q];
        int c = q * 4;
        s += fmaxf(fmaf(v.x, scv[c + 0], shv[c + 0]), 0.f) * wv[c + 0];
        s += fmaxf(fmaf(v.y, scv[c + 1], shv[c + 1]), 0.f) * wv[c + 1];
        s += fmaxf(fmaf(v.z, scv[c + 2], shv[c + 2]), 0.f) * wv[c + 2];
        s += fmaxf(fmaf(v.w, scv[c + 3], shv[c + 3]), 0.f) * wv[c + 3];
    }
    out[r] = s + b3[0];
}

// ---------------------------------------------------------------------------
extern "C" void kernel_launch(void* const* d_in, const int* in_sizes, int n_in,
                              void* d_out, int out_size) {
    const float* x   = (const float*)d_in[0];
    const int*   ei  = (const int*)d_in[1];
    const float* Wl1 = (const float*)d_in[2];
    const float* bl1 = (const float*)d_in[3];
    const float* Wr1 = (const float*)d_in[4];
    const float* Wl2 = (const float*)d_in[5];
    const float* bl2 = (const float*)d_in[6];
    const float* Wr2 = (const float*)d_in[7];
    const float* W1  = (const float*)d_in[8];
    const float* b1  = (const float*)d_in[9];
    const float* g1  = (const float*)d_in[10];
    const float* be1 = (const float*)d_in[11];
    const float* W2  = (const float*)d_in[12];
    const float* b2  = (const float*)d_in[13];
    const float* g2  = (const float*)d_in[14];
    const float* be2 = (const float*)d_in[15];
    const float* W3  = (const float*)d_in[16];
    const float* b3  = (const float*)d_in[17];

    const int N = in_sizes[0] / F_IN;
    const int E = in_sizes[1] / 2;
    const int* src = ei;
    const int* dst = ei + E;

    float* out = (float*)d_out;
    float* h1  = out + N;
    float* h2  = h1 + (size_t)N * HID;

    float* base = nullptr;
    cudaGetSymbolAddress((void**)&base, g_scratch);
    float* invdeg = base;
    float* agg    = invdeg + NMAX;
    float* t1     = agg + (size_t)NMAX * 128;
    float* t2     = t1 + (size_t)NMAX * 128;
    float* sum1   = t2 + (size_t)NMAX * 64;
    float* sumsq1 = sum1 + 128;
    float* sum2   = sumsq1 + 128;
    float* sumsq2 = sum2 + 64;
    float* sc1    = sumsq2 + 64;
    float* sh1    = sc1 + 128;
    float* sc2    = sh1 + 128;
    float* sh2    = sc2 + 64;

    int *deg = nullptr, *off = nullptr, *cur = nullptr, *csr = nullptr;
    int *bsum = nullptr, *boff = nullptr;
    cudaGetSymbolAddress((void**)&deg, g_deg);
    cudaGetSymbolAddress((void**)&off, g_off);
    cudaGetSymbolAddress((void**)&cur, g_cur);
    cudaGetSymbolAddress((void**)&csr, g_csr);
    cudaGetSymbolAddress((void**)&bsum, g_bsum);
    cudaGetSymbolAddress((void**)&boff, g_boff);
    __nv_bfloat16 *wh = nullptr, *wl = nullptr;
    cudaGetSymbolAddress((void**)&wh, g_wh);
    cudaGetSymbolAddress((void**)&wl, g_wl);

    const int TB = 256;
    const int gemm_grid = (N + 63) / 64;      // BM=64 tiles
    const int gather_grid = (N * 32 + TB - 1) / TB;
    const int scan_blocks = (N + 255) / 256;  // 196 <= 256

    // prep + init
    prep_weights<<<(WTOTAL + TB - 1) / TB, TB>>>(Wl1, Wr1, Wl2, Wr2, W1, W2, wh, wl);
    zero_kernel<<<(N + TB - 1) / TB, TB>>>(deg, N);

    // CSR build: deg -> 3-phase parallel scan -> fill
    deg_kernel<<<(E + TB - 1) / TB, TB>>>(dst, deg, E);
    block_sums<<<scan_blocks, 256>>>(deg, bsum, N);
    scan_partials<<<1, 256>>>(bsum, boff, scan_blocks, sum1);
    offsets_kernel<<<scan_blocks, 256>>>(deg, boff, off, cur, invdeg, N, E);
    fill_kernel<<<(E + TB - 1) / TB, TB>>>(src, dst, cur, csr, E);

    // SAGE layer 1
    gather_agg<F_IN / 4><<<gather_grid, TB>>>((const float4*)x, csr, off, invdeg,
                                              (float4*)agg, N);
    mma_gemm<100, 112, 100, 112, 128, true, false, false><<<gemm_grid, TB>>>(
        agg, x, wh + WOFF_L1, wl + WOFF_L1, wh + WOFF_R1, wl + WOFF_R1,
        bl1, nullptr, nullptr, nullptr, nullptr, h1, N);

    // SAGE layer 2
    gather_agg<HID / 4><<<gather_grid, TB>>>((const float4*)h1, csr, off, invdeg,
                                             (float4*)agg, N);
    mma_gemm<128, 128, 128, 128, 128, true, false, false><<<gemm_grid, TB>>>(
        agg, h1, wh + WOFF_L2, wl + WOFF_L2, wh + WOFF_R2, wl + WOFF_R2,
        bl2, nullptr, nullptr, nullptr, nullptr, h2, N);

    // MLP layer 1: t1 = h2@W1 + b1 (+stats)
    mma_gemm<128, 128, 0, 0, 128, false, false, true><<<gemm_grid, TB>>>(
        h2, h2, wh + WOFF_M1, wl + WOFF_M1, wh + WOFF_M1, wl + WOFF_M1,
        b1, nullptr, nullptr, sum1, sumsq1, t1, N);
    bn_finalize_kernel<<<1, 128>>>(sum1, sumsq1, g1, be1, sc1, sh1, 128, 1.0f / (float)N);

    // MLP layer 2: t2 = relu(bn(t1))@W2 + b2 (BN+relu fused into A load, +stats)
    mma_gemm<128, 128, 0, 0, 64, false, true, true><<<gemm_grid, TB>>>(
        t1, t1, wh + WOFF_M2, wl + WOFF_M2, wh + WOFF_M2, wl + WOFF_M2,
        b2, sc1, sh1, sum2, sumsq2, t2, N);
    bn_finalize_kernel<<<1, 64>>>(sum2, sumsq2, g2, be2, sc2, sh2, 64, 1.0f / (float)N);

    // final
    final_kernel<<<(N + TB - 1) / TB, TB>>>(t2, sc2, sh2, W3, b3, out, N);
}

// round 16
// speedup vs baseline: 1.0033x; 1.0013x over previous
#include <cuda_runtime.h>
#include <cuda_bf16.h>
#include <cstdint>

#define NMAX 50000
#define EMAX 800000
#define F_IN 100
#define HID  128
#define H2D  64

// ---- scratch ----
__device__ int   g_deg[NMAX];
__device__ int   g_off[NMAX + 1];
__device__ int   g_cur[NMAX];
__device__ int   g_csr[EMAX];
__device__ int   g_bsum[256];
__device__ int   g_boff[256];
// invdeg | agg[N*128] | t1[N*128] | t2[N*64] | bn(768)
__device__ float g_scratch[NMAX * 321 + 768];

// split weights bf16 hi/lo, transposed [NC][Kpad]
#define WOFF_L1  0
#define WOFF_R1  14336
#define WOFF_L2  28672
#define WOFF_R2  45056
#define WOFF_M1  61440
#define WOFF_M2  77824
#define WTOTAL   86016
__device__ __nv_bfloat16 g_wh[WTOTAL];
__device__ __nv_bfloat16 g_wl[WTOTAL];

// ---------------------------------------------------------------------------
__global__ void zero_kernel(int* __restrict__ p, int n) {
    int i = blockIdx.x * blockDim.x + threadIdx.x;
    for (; i < n; i += gridDim.x * blockDim.x) p[i] = 0;
}

__global__ void deg_kernel(const int* __restrict__ dst, int* __restrict__ deg, int E) {
    int e = blockIdx.x * blockDim.x + threadIdx.x;
    if (e < E) atomicAdd(&deg[dst[e]], 1);
}

// ---- three-phase parallel exclusive scan ----
__global__ void block_sums(const int* __restrict__ deg, int* __restrict__ bsum, int N) {
    int i = blockIdx.x * 256 + threadIdx.x;
    int lane = threadIdx.x & 31, w = threadIdx.x >> 5;
    int v = (i < N) ? deg[i] : 0;
#pragma unroll
    for (int o = 16; o; o >>= 1) v += __shfl_down_sync(~0u, v, o);
    __shared__ int ws[8];
    if (lane == 0) ws[w] = v;
    __syncthreads();
    if (threadIdx.x == 0) {
        int s = 0;
#pragma unroll
        for (int j = 0; j < 8; j++) s += ws[j];
        bsum[blockIdx.x] = s;
    }
}

// 1 block, 256 threads; exclusive-scans nb (<=256) partials; zeroes BN sums
__global__ void scan_partials(const int* __restrict__ bsum, int* __restrict__ boff,
                              int nb, float* __restrict__ bnzero) {
    int t = threadIdx.x, lane = t & 31, w = t >> 5;
    for (int i = t; i < 384; i += 256) bnzero[i] = 0.f;
    int d = (t < nb) ? bsum[t] : 0;
    int v = d;
#pragma unroll
    for (int o = 1; o < 32; o <<= 1) {
        int u = __shfl_up_sync(~0u, v, o);
        if (lane >= o) v += u;
    }
    __shared__ int ws[8];
    if (lane == 31) ws[w] = v;
    __syncthreads();
    int add = 0;
#pragma unroll
    for (int j = 0; j < 8; j++) if (j < w) add += ws[j];
    boff[t] = v - d + add;
}

__global__ void offsets_kernel(const int* __restrict__ deg, const int* __restrict__ boff,
                               int* __restrict__ off, int* __restrict__ cur,
                               float* __restrict__ invdeg, int N, int E) {
    int i = blockIdx.x * 256 + threadIdx.x;
    int t = threadIdx.x, lane = t & 31, w = t >> 5;
    int d = (i < N) ? deg[i] : 0;
    int v = d;
#pragma unroll
    for (int o = 1; o < 32; o <<= 1) {
        int u = __shfl_up_sync(~0u, v, o);
        if (lane >= o) v += u;
    }
    __shared__ int ws[8];
    if (lane == 31) ws[w] = v;
    __syncthreads();
    int add = 0;
#pragma unroll
    for (int j = 0; j < 8; j++) if (j < w) add += ws[j];
    int excl = v - d + add + boff[blockIdx.x];
    if (i < N) {
        off[i] = excl;
        cur[i] = excl;
        invdeg[i] = 1.0f / fmaxf((float)d, 1.0f);
    }
    if (i == 0) off[N] = E;
}

__global__ void fill_kernel(const int* __restrict__ src, const int* __restrict__ dst,
                            int* __restrict__ cur, int* __restrict__ csr, int E) {
    int e = blockIdx.x * blockDim.x + threadIdx.x;
    if (e < E) {
        int pos = atomicAdd(&cur[dst[e]], 1);
        csr[pos] = src[e];
    }
}

// split + transpose all 6 weight matrices into bf16 hi/lo, [NC][Kpad]
__global__ void prep_weights(const float* __restrict__ Wl1, const float* __restrict__ Wr1,
                             const float* __restrict__ Wl2, const float* __restrict__ Wr2,
                             const float* __restrict__ W1,  const float* __restrict__ W2,
                             __nv_bfloat16* __restrict__ wh, __nv_bfloat16* __restrict__ wl) {
    int i = blockIdx.x * blockDim.x + threadIdx.x;
    if (i >= WTOTAL) return;
    const float* W; int K, KP, NC, local;
    if (i < WOFF_L2) {
        if (i < WOFF_R1) { W = Wl1; local = i; }
        else             { W = Wr1; local = i - WOFF_R1; }
        K = 100; KP = 112; NC = 128;
    } else if (i < WOFF_M2) {
        if (i < WOFF_R2)      { W = Wl2; local = i - WOFF_L2; }
        else if (i < WOFF_M1) { W = Wr2; local = i - WOFF_R2; }
        else                  { W = W1;  local = i - WOFF_M1; }
        K = 128; KP = 128; NC = 128;
    } else {
        W = W2; local = i - WOFF_M2; K = 128; KP = 128; NC = 64;
    }
    int n = local / KP, k = local - n * KP;
    float v = (k < K) ? W[k * NC + n] : 0.f;
    __nv_bfloat16 h = __float2bfloat16_rn(v);
    wh[i] = h;
    wl[i] = __float2bfloat16_rn(v - __bfloat162float(h));
}

// ---------------------------------------------------------------------------
// gather aggregation: warp per dst node, lane owns one float4 feature group.
// ---------------------------------------------------------------------------
template <int F4>
__global__ void gather_agg(const float4* __restrict__ x4, const int* __restrict__ csr,
                           const int* __restrict__ off, const float* __restrict__ invdeg,
                           float4* __restrict__ agg, int N) {
    int w = (blockIdx.x * blockDim.x + threadIdx.x) >> 5;
    int lane = threadIdx.x & 31;
    if (w >= N || lane >= F4) return;
    int o = off[w];
    int d = off[w + 1] - o;
    float4 acc = make_float4(0.f, 0.f, 0.f, 0.f);
    int j = 0;
    for (; j + 2 <= d; j += 2) {
        int s0 = __ldg(&csr[o + j]);
        int s1 = __ldg(&csr[o + j + 1]);
        float4 v0 = __ldg(&x4[(size_t)s0 * F4 + lane]);
        float4 v1 = __ldg(&x4[(size_t)s1 * F4 + lane]);
        acc.x += v0.x; acc.y += v0.y; acc.z += v0.z; acc.w += v0.w;
        acc.x += v1.x; acc.y += v1.y; acc.z += v1.z; acc.w += v1.w;
    }
    if (j < d) {
        int s0 = __ldg(&csr[o + j]);
        float4 v0 = __ldg(&x4[(size_t)s0 * F4 + lane]);
        acc.x += v0.x; acc.y += v0.y; acc.z += v0.z; acc.w += v0.w;
    }
    float iv = invdeg[w];
    agg[(size_t)w * F4 + lane] = make_float4(acc.x * iv, acc.y * iv, acc.z * iv, acc.w * iv);
}

// ---------------------------------------------------------------------------
// Tensor-core GEMM, two-term bf16 split (3 MMAs), ldmatrix frags,
// double-buffered smem, cp.async for B tiles. BM=64 tiles for occupancy 3.
// ---------------------------------------------------------------------------
__device__ __forceinline__ uint32_t smem_u32(const void* p) {
    return (uint32_t)__cvta_generic_to_shared(p);
}

#define LDSM4(R, a)                                                             \
    asm volatile("ldmatrix.sync.aligned.m8n8.x4.shared.b16 {%0,%1,%2,%3}, [%4];"\
                 : "=r"((R)[0]), "=r"((R)[1]), "=r"((R)[2]), "=r"((R)[3])       \
                 : "r"(a))

#define MMA16816(C, A, b0, b1)                                                  \
    asm volatile("mma.sync.aligned.m16n8k16.row.col.f32.bf16.bf16.f32 "         \
                 "{%0,%1,%2,%3}, {%4,%5,%6,%7}, {%8,%9}, {%0,%1,%2,%3};"        \
                 : "+f"((C)[0]), "+f"((C)[1]), "+f"((C)[2]), "+f"((C)[3])       \
                 : "r"((A)[0]), "r"((A)[1]), "r"((A)[2]), "r"((A)[3]),          \
                   "r"(b0), "r"(b1))

#define CP_ASYNC16(smem_addr, gptr)                                             \
    asm volatile("cp.async.ca.shared.global [%0], [%1], 16;"                    \
                 :: "r"(smem_addr), "l"(gptr) : "memory")

template <int K1, int KP1, int K2, int KP2, int NC, bool RELU, bool BNRELU, bool STATS>
__global__ __launch_bounds__(256, 3) void mma_gemm(
    const float* __restrict__ A1, const float* __restrict__ A2,
    const __nv_bfloat16* __restrict__ B1h, const __nv_bfloat16* __restrict__ B1l,
    const __nv_bfloat16* __restrict__ B2h, const __nv_bfloat16* __restrict__ B2l,
    const float* __restrict__ bias,
    const float* __restrict__ bnsc, const float* __restrict__ bnsh,
    float* __restrict__ gsum, float* __restrict__ gsumsq,
    float* __restrict__ out, int N) {

    // BM = 64. 8 warps: 4 along M (16 rows each), 2 along N.
    constexpr int NCW = NC / 2;            // 64 or 32 cols per warp
    constexpr int NT = NCW / 8;            // 8 or 4
    constexpr int NH = NCW / 32;           // 2 or 1 (16-col ldsm pairs per half)
    constexpr int C1 = KP1 / 16, C2 = KP2 / 16, NCH = C1 + C2;
    constexpr int BCP = NC * 2;            // 16B chunks per B array per stage

    __shared__ __align__(16) __nv_bfloat16 Ah[2][64][24], Al[2][64][24];
    __shared__ __align__(16) __nv_bfloat16 Bh[2][NC][24],  Bl[2][NC][24];

    const int tid = threadIdx.x, lane = tid & 31, wid = tid >> 5;
    const int wm = wid >> 1, wn = wid & 1;
    const int row0 = blockIdx.x * 64;

    float acc[NT][4];
#pragma unroll
    for (int nt = 0; nt < NT; nt++)
#pragma unroll
        for (int q = 0; q < 4; q++) acc[nt][q] = 0.f;

    float2 av[2];                 // A staging (fp32 -> bf16 split conversion)
    const int kk2 = (tid & 7) * 2;
    const int mr  = tid >> 3;     // 0..31

    auto issue_B = [&](int ch, int st) {
        const __nv_bfloat16 *gh, *gl; int KPE, k0;
        if (ch < C1) { gh = B1h; gl = B1l; KPE = KP1; k0 = ch * 16; }
        else         { gh = B2h; gl = B2l; KPE = KP2; k0 = (ch - C1) * 16; }
#pragma unroll
        for (int j = 0; j < (BCP + 255) / 256; j++) {
            int w = tid + j * 256;
            if (BCP < 256 && w >= BCP) break;
            int n = w >> 1, half = w & 1;
            const __nv_bfloat16* srch = gh + n * KPE + k0 + half * 8;
            const __nv_bfloat16* srcl = gl + n * KPE + k0 + half * 8;
            CP_ASYNC16(smem_u32(&Bh[st][n][half * 8]), srch);
            CP_ASYNC16(smem_u32(&Bl[st][n][half * 8]), srcl);
        }
        asm volatile("cp.async.commit_group;" ::: "memory");
    };

    auto load_A = [&](int ch) {
        const float* A; int K, k0; bool bn;
        if (ch < C1) { A = A1; K = K1; k0 = ch * 16; bn = BNRELU; }
        else         { A = A2; K = K2; k0 = (ch - C1) * 16; bn = false; }
        const int kt = k0 + kk2;
        float s0 = 1.f, h0 = 0.f, s1 = 1.f, h1 = 0.f;
        if (BNRELU && bn) {
            if (kt < K)     { s0 = bnsc[kt];     h0 = bnsh[kt]; }
            if (kt + 1 < K) { s1 = bnsc[kt + 1]; h1 = bnsh[kt + 1]; }
        }
#pragma unroll
        for (int i = 0; i < 2; i++) {
            int row = row0 + mr + i * 32;
            float v0 = 0.f, v1 = 0.f;
            if (row < N) {
                const float* ar = A + (size_t)row * K;
                if (kt + 1 < K) { float2 tv = *(const float2*)(ar + kt); v0 = tv.x; v1 = tv.y; }
                else if (kt < K) { v0 = ar[kt]; }
            }
            if (BNRELU && bn) {
                v0 = fmaxf(fmaf(v0, s0, h0), 0.f);
                v1 = fmaxf(fmaf(v1, s1, h1), 0.f);
            }
            av[i] = make_float2(v0, v1);
        }
    };

    auto store_A = [&](int st) {
#pragma unroll
        for (int i = 0; i < 2; i++) {
            int m = mr + i * 32;
            float2 v = av[i];
            __nv_bfloat162 h2 = __float22bfloat162_rn(v);
            float2 hf = __bfloat1622float2(h2);
            __nv_bfloat162 l2 = __float22bfloat162_rn(make_float2(v.x - hf.x, v.y - hf.y));
            *(uint32_t*)&Ah[st][m][kk2] = *(uint32_t*)&h2;
            *(uint32_t*)&Al[st][m][kk2] = *(uint32_t*)&l2;
        }
    };

    const int arow = (lane & 15), acol = ((lane >> 4) << 3);
    const int brow = (lane & 7) + ((lane & 16) >> 1), bcol = (lane & 8);

    // prologue: fill stage 0
    issue_B(0, 0);
    load_A(0);
    store_A(0);
    asm volatile("cp.async.wait_group 0;" ::: "memory");
    __syncthreads();

    for (int ch = 0; ch < NCH; ch++) {
        const int st = ch & 1;
        if (ch + 1 < NCH) {
            issue_B(ch + 1, st ^ 1);  // async, lands during MMAs
            load_A(ch + 1);           // global loads in flight during MMAs
        }

        uint32_t fah[4], fal[4];
        {
            int m0 = wm * 16;
            LDSM4(fah, smem_u32(&Ah[st][m0 + arow][acol]));
            LDSM4(fal, smem_u32(&Al[st][m0 + arow][acol]));
        }
#pragma unroll
        for (int nh = 0; nh < NH; nh++) {
#pragma unroll
            for (int p = 0; p < 2; p++) {
                uint32_t fbh[4], fbl[4];
                int n0 = wn * NCW + (nh * 2 + p) * 16;
                LDSM4(fbh, smem_u32(&Bh[st][n0 + brow][bcol]));
                LDSM4(fbl, smem_u32(&Bl[st][n0 + brow][bcol]));
#pragma unroll
                for (int hh = 0; hh < 2; hh++) {
                    int nt = nh * 4 + p * 2 + hh;
                    MMA16816(acc[nt], fah, fbh[2 * hh], fbh[2 * hh + 1]);
                    MMA16816(acc[nt], fah, fbl[2 * hh], fbl[2 * hh + 1]);
                    MMA16816(acc[nt], fal, fbh[2 * hh], fbh[2 * hh + 1]);
                }
            }
        }
        if (ch + 1 < NCH) {
            store_A(st ^ 1);
            asm volatile("cp.async.wait_group 0;" ::: "memory");
        }
        __syncthreads();
    }

    // ---- epilogue ----
    const int g = lane >> 2, tg = lane & 3;
    float* s_st = reinterpret_cast<float*>(&Ah[0][0][0]);  // reuse smem
    if (STATS) {
        for (int i = tid; i < 2 * NC; i += 256) s_st[i] = 0.f;
        __syncthreads();
    }

    float ls[NT][2], lq[NT][2];
    if (STATS) {
#pragma unroll
        for (int nt = 0; nt < NT; nt++) { ls[nt][0] = ls[nt][1] = lq[nt][0] = lq[nt][1] = 0.f; }
    }

    {
        int rowA = row0 + wm * 16 + g;
        int rowB = rowA + 8;
#pragma unroll
        for (int nt = 0; nt < NT; nt++) {
            int col = wn * NCW + nt * 8 + tg * 2;
            float b0 = bias[col], b1 = bias[col + 1];
            float v0 = acc[nt][0] + b0, v1 = acc[nt][1] + b1;
            float v2 = acc[nt][2] + b0, v3 = acc[nt][3] + b1;
            if (RELU) {
                v0 = fmaxf(v0, 0.f); v1 = fmaxf(v1, 0.f);
                v2 = fmaxf(v2, 0.f); v3 = fmaxf(v3, 0.f);
            }
            if (rowA < N) {
                *(float2*)&out[(size_t)rowA * NC + col] = make_float2(v0, v1);
                if (STATS) {
                    ls[nt][0] += v0; lq[nt][0] += v0 * v0;
                    ls[nt][1] += v1; lq[nt][1] += v1 * v1;
                }
            }
            if (rowB < N) {
                *(float2*)&out[(size_t)rowB * NC + col] = make_float2(v2, v3);
                if (STATS) {
                    ls[nt][0] += v2; lq[nt][0] += v2 * v2;
                    ls[nt][1] += v3; lq[nt][1] += v3 * v3;
                }
            }
        }
    }

    if (STATS) {
#pragma unroll
        for (int nt = 0; nt < NT; nt++) {
            int col = wn * NCW + nt * 8 + tg * 2;
            atomicAdd(&s_st[col], ls[nt][0]);
            atomicAdd(&s_st[NC + col], lq[nt][0]);
            atomicAdd(&s_st[col + 1], ls[nt][1]);
            atomicAdd(&s_st[NC + col + 1], lq[nt][1]);
        }
        __syncthreads();
        for (int i = tid; i < NC; i += 256) {
            atomicAdd(&gsum[i], s_st[i]);
            atomicAdd(&gsumsq[i], s_st[NC + i]);
        }
    }
}

// ---------------------------------------------------------------------------
__global__ void bn_finalize_kernel(const float* __restrict__ gsum, const float* __restrict__ gsumsq,
                                   const float* __restrict__ gamma, const float* __restrict__ beta,
                                   float* __restrict__ sc, float* __restrict__ sh,
                                   int NC, float invN) {
    int c = threadIdx.x;
    if (c < NC) {
        float m = gsum[c] * invN;
        float var = gsumsq[c] * invN - m * m;
        float inv = rsqrtf(var + 1e-5f);
        float s = inv * gamma[c];
        sc[c] = s;
        sh[c] = beta[c] - m * s;
    }
}

__global__ void final_kernel(const float* __restrict__ t2,
                             const float* __restrict__ sc, const float* __restrict__ sh,
                             const float* __restrict__ W3, const float* __restrict__ b3,
                             float* __restrict__ out, int N) {
    __shared__ float wv[64], scv[64], shv[64];
    if (threadIdx.x < 64) {
        wv[threadIdx.x] = W3[threadIdx.x];
        scv[threadIdx.x] = sc[threadIdx.x];
        shv[threadIdx.x] = sh[threadIdx.x];
    }
    __syncthreads();
    int r = blockIdx.x * blockDim.x + threadIdx.x;
    if (r >= N) return;
    const float4* row = (const float4*)(t2 + (size_t)r * 64);
    float s = 0.f;
#pragma unroll
    for (int q = 0; q < 16; q++) {
        float4 v = row[q];
        int c = q * 4;
        s += fmaxf(fmaf(v.x, scv[c + 0], shv[c + 0]), 0.f) * wv[c + 0];
        s += fmaxf(fmaf(v.y, scv[c + 1], shv[c + 1]), 0.f) * wv[c + 1];
        s += fmaxf(fmaf(v.z, scv[c + 2], shv[c + 2]), 0.f) * wv[c + 2];
        s += fmaxf(fmaf(v.w, scv[c + 3], shv[c + 3]), 0.f) * wv[c + 3];
    }
    out[r] = s + b3[0];
}

// ---------------------------------------------------------------------------
extern "C" void kernel_launch(void* const* d_in, const int* in_sizes, int n_in,
                              void* d_out, int out_size) {
    const float* x   = (const float*)d_in[0];
    const int*   ei  = (const int*)d_in[1];
    const float* Wl1 = (const float*)d_in[2];
    const float* bl1 = (const float*)d_in[3];
    const float* Wr1 = (const float*)d_in[4];
    const float* Wl2 = (const float*)d_in[5];
    const float* bl2 = (const float*)d_in[6];
    const float* Wr2 = (const float*)d_in[7];
    const float* W1  = (const float*)d_in[8];
    const float* b1  = (const float*)d_in[9];
    const float* g1  = (const float*)d_in[10];
    const float* be1 = (const float*)d_in[11];
    const float* W2  = (const float*)d_in[12];
    const float* b2  = (const float*)d_in[13];
    const float* g2  = (const float*)d_in[14];
    const float* be2 = (const float*)d_in[15];
    const float* W3  = (const float*)d_in[16];
    const float* b3  = (const float*)d_in[17];

    const int N = in_sizes[0] / F_IN;
    const int E = in_sizes[1] / 2;
    const int* src = ei;
    const int* dst = ei + E;

    float* out = (float*)d_out;
    float* h1  = out + N;
    float* h2  = h1 + (size_t)N * HID;

    float* base = nullptr;
    cudaGetSymbolAddress((void**)&base, g_scratch);
    float* invdeg = base;
    float* agg    = invdeg + NMAX;
    float* t1     = agg + (size_t)NMAX * 128;
    float* t2     = t1 + (size_t)NMAX * 128;
    float* sum1   = t2 + (size_t)NMAX * 64;
    float* sumsq1 = sum1 + 128;
    float* sum2   = sumsq1 + 128;
    float* sumsq2 = sum2 + 64;
    float* sc1    = sumsq2 + 64;
    float* sh1    = sc1 + 128;
    float* sc2    = sh1 + 128;
    float* sh2    = sc2 + 64;

    int *deg = nullptr, *off = nullptr, *cur = nullptr, *csr = nullptr;
    int *bsum = nullptr, *boff = nullptr;
    cudaGetSymbolAddress((void**)&deg, g_deg);
    cudaGetSymbolAddress((void**)&off, g_off);
    cudaGetSymbolAddress((void**)&cur, g_cur);
    cudaGetSymbolAddress((void**)&csr, g_csr);
    cudaGetSymbolAddress((void**)&bsum, g_bsum);
    cudaGetSymbolAddress((void**)&boff, g_boff);
    __nv_bfloat16 *wh = nullptr, *wl = nullptr;
    cudaGetSymbolAddress((void**)&wh, g_wh);
    cudaGetSymbolAddress((void**)&wl, g_wl);

    const int TB = 256;
    const int gemm_grid = (N + 63) / 64;      // BM=64 tiles
    const int gather_grid = (N * 32 + TB - 1) / TB;
    const int scan_blocks = (N + 255) / 256;  // 196 <= 256

    // prep + init
    prep_weights<<<(WTOTAL + TB - 1) / TB, TB>>>(Wl1, Wr1, Wl2, Wr2, W1, W2, wh, wl);
    zero_kernel<<<(N + TB - 1) / TB, TB>>>(deg, N);

    // CSR build: deg -> 3-phase parallel scan -> fill
    deg_kernel<<<(E + TB - 1) / TB, TB>>>(dst, deg, E);
    block_sums<<<scan_blocks, 256>>>(deg, bsum, N);
    scan_partials<<<1, 256>>>(bsum, boff, scan_blocks, sum1);
    offsets_kernel<<<scan_blocks, 256>>>(deg, boff, off, cur, invdeg, N, E);
    fill_kernel<<<(E + TB - 1) / TB, TB>>>(src, dst, cur, csr, E);

    // SAGE layer 1
    gather_agg<F_IN / 4><<<gather_grid, TB>>>((const float4*)x, csr, off, invdeg,
                                              (float4*)agg, N);
    mma_gemm<100, 112, 100, 112, 128, true, false, false><<<gemm_grid, TB>>>(
        agg, x, wh + WOFF_L1, wl + WOFF_L1, wh + WOFF_R1, wl + WOFF_R1,
        bl1, nullptr, nullptr, nullptr, nullptr, h1, N);

    // SAGE layer 2
    gather_agg<HID / 4><<<gather_grid, TB>>>((const float4*)h1, csr, off, invdeg,
                                             (float4*)agg, N);
    mma_gemm<128, 128, 128, 128, 128, true, false, false><<<gemm_grid, TB>>>(
        agg, h1, wh + WOFF_L2, wl + WOFF_L2, wh + WOFF_R2, wl + WOFF_R2,
        bl2, nullptr, nullptr, nullptr, nullptr, h2, N);

    // MLP layer 1: t1 = h2@W1 + b1 (+stats)
    mma_gemm<128, 128, 0, 0, 128, false, false, true><<<gemm_grid, TB>>>(
        h2, h2, wh + WOFF_M1, wl + WOFF_M1, wh + WOFF_M1, wl + WOFF_M1,
        b1, nullptr, nullptr, sum1, sumsq1, t1, N);
    bn_finalize_kernel<<<1, 128>>>(sum1, sumsq1, g1, be1, sc1, sh1, 128, 1.0f / (float)N);

    // MLP layer 2: t2 = relu(bn(t1))@W2 + b2 (BN+relu fused into A load, +stats)
    mma_gemm<128, 128, 0, 0, 64, false, true, true><<<gemm_grid, TB>>>(
        t1, t1, wh + WOFF_M2, wl + WOFF_M2, wh + WOFF_M2, wl + WOFF_M2,
        b2, sc1, sh1, sum2, sumsq2, t2, N);
    bn_finalize_kernel<<<1, 64>>>(sum2, sumsq2, g2, be2, sc2, sh2, 64, 1.0f / (float)N);

    // final
    final_kernel<<<(N + TB - 1) / TB, TB>>>(t2, sc2, sh2, W3, b3, out, N);
}